// round 1
// baseline (speedup 1.0000x reference)
#include <cuda_runtime.h>
#include <math.h>

// Problem constants
#define B_SZ 4096
#define K_SZ 64
#define D_SZ 8
#define F_SZ 2048
#define N_SZ (K_SZ * 2 * D_SZ)   // 1024
#define NPAIR (K_SZ * (K_SZ + 1) / 2)  // 2080

// Output layout: [task_probs (B)] [concept_probs (B*K)] [cond (B*K*K)]
#define OUT_CONCEPT_OFF (B_SZ)
#define OUT_COND_OFF (B_SZ + B_SZ * K_SZ)

// Scratch (allocation-free: __device__ globals)
__device__ float g_theta[(size_t)B_SZ * N_SZ];          // 16 MB raw GEMM result
__device__ float g_z[(size_t)B_SZ * K_SZ * D_SZ];       // 8 MB
__device__ float g_Zc[(size_t)B_SZ * K_SZ * D_SZ];      // 8 MB
__device__ float g_lvbox2[B_SZ * K_SZ];                 // log2 soft volume per box
__device__ float g_boxsum[B_SZ];                        // flat_boxes @ Wbox partial

// ---------------------------------------------------------------------------
// helpers
// ---------------------------------------------------------------------------
__device__ __forceinline__ float softplus_f(float x) {
    // stable: max(x,0) + log1p(exp(-|x|))
    float e = __expf(-fabsf(x));
    return fmaxf(x, 0.0f) + __logf(1.0f + e);
}

// log2 of soft side length: log2( softplus(2*(Z-z)) / 2 ), clamped at EPS=1e-23
__device__ __forceinline__ float log2_side(float z, float Z) {
    float x = 2.0f * (Z - z);
    float sp = fmaxf(x, 0.0f) + __logf(1.0f + __expf(-fabsf(x)));
    float side = 0.5f * sp;
    return __log2f(fmaxf(side, 1e-23f));
}

__device__ __forceinline__ float sigmoid_f(float x) {
    return 1.0f / (1.0f + __expf(-x));
}

// ---------------------------------------------------------------------------
// Kernel 1: GEMM  theta[b, k*16+d] = sum_f features[b,f] * Wp[k,f,d]
// A: [4096, 2048] row-major.  W logical [f, n] at Wp[(n>>4)*32768 + f*16 + (n&15)]
// 128x128 tile, BK=8, 256 threads, 8x8 micro-tile.
// ---------------------------------------------------------------------------
__global__ __launch_bounds__(256, 2)
void gemm_kernel(const float* __restrict__ A, const float* __restrict__ W)
{
    __shared__ __align__(16) float As[8][128];
    __shared__ __align__(16) float Bs[8][128];

    const int tid = threadIdx.x;
    const int bx = blockIdx.x;   // n block: 0..7
    const int by = blockIdx.y;   // m block: 0..31

    const int arow = tid >> 1;            // 0..127
    const int acol = (tid & 1) << 2;      // 0 or 4
    const int brow = tid >> 5;            // 0..7   (f within tile)
    const int bcol = (tid & 31) << 2;     // 0..124 (n within tile, float4)

    const int tx = tid & 15;
    const int ty = tid >> 4;

    const float* Aptr = A + (size_t)(by * 128 + arow) * F_SZ + acol;
    const int ng = bx * 128 + bcol;       // global n of this thread's B float4
    const float* Bptr = W + (size_t)(ng >> 4) * (F_SZ * 16) + (ng & 15) + brow * 16;

    float acc[8][8];
#pragma unroll
    for (int i = 0; i < 8; i++)
#pragma unroll
        for (int j = 0; j < 8; j++) acc[i][j] = 0.0f;

    for (int k0 = 0; k0 < F_SZ; k0 += 8) {
        float4 av = *(const float4*)(Aptr + k0);
        float4 bv = *(const float4*)(Bptr + (size_t)k0 * 16);
        __syncthreads();
        As[acol + 0][arow] = av.x;
        As[acol + 1][arow] = av.y;
        As[acol + 2][arow] = av.z;
        As[acol + 3][arow] = av.w;
        *(float4*)&Bs[brow][bcol] = bv;
        __syncthreads();
#pragma unroll
        for (int kk = 0; kk < 8; kk++) {
            float a[8], bb[8];
            *(float4*)&a[0]  = *(const float4*)&As[kk][ty * 8];
            *(float4*)&a[4]  = *(const float4*)&As[kk][ty * 8 + 4];
            *(float4*)&bb[0] = *(const float4*)&Bs[kk][tx * 8];
            *(float4*)&bb[4] = *(const float4*)&Bs[kk][tx * 8 + 4];
#pragma unroll
            for (int i = 0; i < 8; i++)
#pragma unroll
                for (int j = 0; j < 8; j++)
                    acc[i][j] = fmaf(a[i], bb[j], acc[i][j]);
        }
    }

    float* Cp = g_theta + (size_t)(by * 128 + ty * 8) * N_SZ + bx * 128 + tx * 8;
#pragma unroll
    for (int i = 0; i < 8; i++) {
        float4 v0 = make_float4(acc[i][0], acc[i][1], acc[i][2], acc[i][3]);
        float4 v1 = make_float4(acc[i][4], acc[i][5], acc[i][6], acc[i][7]);
        *(float4*)(Cp + (size_t)i * N_SZ)     = v0;
        *(float4*)(Cp + (size_t)i * N_SZ + 4) = v1;
    }
}

// ---------------------------------------------------------------------------
// Kernel 2: per-box epilogue. One block per b, 64 threads (one per k).
// Computes z, Z, concept_probs, lv_box (log2), and box part of final logit.
// ---------------------------------------------------------------------------
__global__ __launch_bounds__(64)
void box_kernel(const float* __restrict__ bp, const float* __restrict__ Wprob,
                const float* __restrict__ bprob, const float* __restrict__ Wbox,
                float* __restrict__ out)
{
    const int b = blockIdx.x;
    const int k = threadIdx.x;

    const float* th  = g_theta + (size_t)b * N_SZ + k * 16;
    const float* bpk = bp + k * 16;

    float z[8], Zb[8];
#pragma unroll
    for (int d = 0; d < 8; d++) {
        float zv = th[d] + bpk[d];
        float u  = th[8 + d] + bpk[8 + d];
        z[d]  = zv;
        Zb[d] = zv + softplus_f(u);
    }

    // concept logit
    const float* wp = Wprob + k * 16;
    float logit = bprob[k];
#pragma unroll
    for (int d = 0; d < 8; d++)
        logit += z[d] * wp[d] + Zb[d] * wp[8 + d];
    float p = sigmoid_f(logit);
    out[OUT_CONCEPT_OFF + b * K_SZ + k] = p;

    // log2 soft volume of the box
    float lv2 = 0.0f;
#pragma unroll
    for (int d = 0; d < 8; d++)
        lv2 += log2_side(z[d], Zb[d]);
    g_lvbox2[b * K_SZ + k] = lv2;

    // stash z/Z for pairwise kernel
    float* gz = g_z  + (size_t)b * (K_SZ * D_SZ) + k * 8;
    float* gZ = g_Zc + (size_t)b * (K_SZ * D_SZ) + k * 8;
#pragma unroll
    for (int d = 0; d < 8; d++) { gz[d] = z[d]; gZ[d] = Zb[d]; }

    // box contribution to final logit: p * sum_d (z*Wbox_z + Z*Wbox_Z)
    const float* wb = Wbox + k * 16;
    float c = 0.0f;
#pragma unroll
    for (int d = 0; d < 8; d++)
        c += z[d] * wb[d] + Zb[d] * wb[8 + d];
    c *= p;

    __shared__ float red[64];
    red[k] = c;
    __syncthreads();
    if (k == 0) {
        float s = 0.0f;
        for (int i = 0; i < 64; i++) s += red[i];
        g_boxsum[b] = s;
    }
}

// ---------------------------------------------------------------------------
// Kernel 3: pairwise intersections. One block per b, 256 threads.
// lv_int is symmetric in (i,j): compute each unordered pair once,
// emit cond[i,j] and cond[j,i]. Stage cond in smem, write coalesced float4.
// Also computes flat_rel @ Wrel and the final task logit.
// ---------------------------------------------------------------------------
__global__ __launch_bounds__(256)
void pair_kernel(const float* __restrict__ Wrel, const float* __restrict__ bbox,
                 const float* __restrict__ brel, float* __restrict__ out)
{
    const int b = blockIdx.x;
    const int tid = threadIdx.x;

    __shared__ __align__(16) float sz[K_SZ * D_SZ];   // 512
    __shared__ __align__(16) float sZ[K_SZ * D_SZ];   // 512
    __shared__ __align__(16) float slv[K_SZ];         // 64
    __shared__ __align__(16) float sw[K_SZ * K_SZ];   // 4096
    __shared__ __align__(16) float sc[K_SZ * K_SZ];   // 4096
    __shared__ float rr[8];

    const float* gz = g_z  + (size_t)b * (K_SZ * D_SZ);
    const float* gZ = g_Zc + (size_t)b * (K_SZ * D_SZ);
    for (int i = tid; i < K_SZ * D_SZ; i += 256) { sz[i] = gz[i]; sZ[i] = gZ[i]; }
    if (tid < K_SZ) slv[tid] = g_lvbox2[b * K_SZ + tid];
    for (int i = tid; i < K_SZ * K_SZ; i += 256) sw[i] = Wrel[i];
    __syncthreads();

    for (int p = tid; p < NPAIR; p += 256) {
        // map p -> (i, j) with j <= i  (lower-triangular enumeration)
        int i = (int)((sqrtf(8.0f * (float)p + 1.0f) - 1.0f) * 0.5f);
        while ((i + 1) * (i + 2) / 2 <= p) ++i;
        while (i * (i + 1) / 2 > p) --i;
        int j = p - i * (i + 1) / 2;

        const float* zi = sz + i * 8;
        const float* zj = sz + j * 8;
        const float* Zi = sZ + i * 8;
        const float* Zj = sZ + j * 8;

        float lv2 = 0.0f;
#pragma unroll
        for (int d = 0; d < 8; d++) {
            float a = zi[d], c = zj[d];
            float zint = fmaxf(a, c)
                       + 0.1f * __logf(1.0f + __expf(-10.0f * fabsf(a - c)));
            float A2 = Zi[d], C2 = Zj[d];
            float Zint = fminf(A2, C2)
                       - 0.1f * __logf(1.0f + __expf(-10.0f * fabsf(A2 - C2)));
            lv2 += log2_side(zint, Zint);
        }

        float cij = exp2f(lv2 - slv[j]);
        cij = fminf(fmaxf(cij, 1e-6f), 1.0f - 1e-6f);
        float cji = exp2f(lv2 - slv[i]);
        cji = fminf(fmaxf(cji, 1e-6f), 1.0f - 1e-6f);
        sc[i * K_SZ + j] = cij;
        sc[j * K_SZ + i] = cji;   // i == j: same slot, same value
    }
    __syncthreads();

    // coalesced writeout of cond + flat_rel @ Wrel accumulation
    float acc = 0.0f;
    float4* condout = (float4*)(out + OUT_COND_OFF + (size_t)b * (K_SZ * K_SZ));
    for (int q = tid; q < (K_SZ * K_SZ) / 4; q += 256) {
        float4 v = *(const float4*)&sc[q * 4];
        float4 w = *(const float4*)&sw[q * 4];
        condout[q] = v;
        acc += v.x * w.x + v.y * w.y + v.z * w.z + v.w * w.w;
    }

    // block reduce
#pragma unroll
    for (int off = 16; off > 0; off >>= 1)
        acc += __shfl_down_sync(0xffffffffu, acc, off);
    if ((tid & 31) == 0) rr[tid >> 5] = acc;
    __syncthreads();
    if (tid == 0) {
        float s = 0.0f;
        for (int w = 0; w < 8; w++) s += rr[w];
        float logit = g_boxsum[b] + bbox[0] + s + brel[0];
        out[b] = sigmoid_f(logit);
    }
}

// ---------------------------------------------------------------------------
extern "C" void kernel_launch(void* const* d_in, const int* in_sizes, int n_in,
                              void* d_out, int out_size)
{
    const float* features = (const float*)d_in[0];
    const float* Wp       = (const float*)d_in[1];
    const float* bp       = (const float*)d_in[2];
    const float* Wprob    = (const float*)d_in[3];
    const float* bprob    = (const float*)d_in[4];
    const float* Wbox     = (const float*)d_in[5];
    const float* bbox     = (const float*)d_in[6];
    const float* Wrel     = (const float*)d_in[7];
    const float* brel     = (const float*)d_in[8];
    float* out = (float*)d_out;

    dim3 g1(N_SZ / 128, B_SZ / 128);   // (8, 32)
    gemm_kernel<<<g1, 256>>>(features, Wp);
    box_kernel<<<B_SZ, 64>>>(bp, Wprob, bprob, Wbox, out);
    pair_kernel<<<B_SZ, 256>>>(Wrel, bbox, brel, out);
}

// round 2
// speedup vs baseline: 1.1959x; 1.1959x over previous
#include <cuda_runtime.h>
#include <math.h>
#include <stdint.h>

// Problem constants
#define B_SZ 4096
#define K_SZ 64
#define D_SZ 8
#define F_SZ 2048
#define N_SZ (K_SZ * 2 * D_SZ)        // 1024
#define NPAIR (K_SZ * (K_SZ + 1) / 2) // 2080

// Output layout: [task_probs (B)] [concept_probs (B*K)] [cond (B*K*K)]
#define OUT_CONCEPT_OFF (B_SZ)
#define OUT_COND_OFF (B_SZ + B_SZ * K_SZ)

// Scratch
__device__ float g_theta[(size_t)B_SZ * N_SZ];
__device__ float g_z[(size_t)B_SZ * K_SZ * D_SZ];
__device__ float g_Zc[(size_t)B_SZ * K_SZ * D_SZ];
__device__ float g_lvbox2[B_SZ * K_SZ];
__device__ float g_boxsum[B_SZ];

// ---------------------------------------------------------------------------
// helpers
// ---------------------------------------------------------------------------
__device__ __forceinline__ float softplus_f(float x) {
    float e = __expf(-fabsf(x));
    return fmaxf(x, 0.0f) + __logf(1.0f + e);
}

__device__ __forceinline__ float log2_side(float z, float Z) {
    float x = 2.0f * (Z - z);
    float sp = fmaxf(x, 0.0f) + __logf(1.0f + __expf(-fabsf(x)));
    float side = 0.5f * sp;
    return __log2f(fmaxf(side, 1e-23f));
}

__device__ __forceinline__ float sigmoid_f(float x) {
    return 1.0f / (1.0f + __expf(-x));
}

__device__ __forceinline__ float tf32_rna(float x) {
    float r;
    asm("cvt.rna.tf32.f32 %0, %1;" : "=f"(r) : "f"(x));
    return r;
}

__device__ __forceinline__ void mma_tf32(float* c,
                                         uint32_t a0, uint32_t a1, uint32_t a2, uint32_t a3,
                                         uint32_t b0, uint32_t b1) {
    asm volatile(
        "mma.sync.aligned.m16n8k8.row.col.f32.tf32.tf32.f32 "
        "{%0,%1,%2,%3}, {%4,%5,%6,%7}, {%8,%9}, {%0,%1,%2,%3};"
        : "+f"(c[0]), "+f"(c[1]), "+f"(c[2]), "+f"(c[3])
        : "r"(a0), "r"(a1), "r"(a2), "r"(a3), "r"(b0), "r"(b1));
}

// ---------------------------------------------------------------------------
// Kernel 1: 3xTF32 tensor-core GEMM.
// C[4096,1024] = A[4096,2048] x W[2048,1024]
// W logical [f, n] at Wp[(n>>4)*F*16 + f*16 + (n&15)]
// Block tile 128x128, BK=16, 256 threads (8 warps: 2 m-warps x 4 n-warps),
// warp tile 64x32. A/B split into tf32 hi/lo planes in smem.
// ---------------------------------------------------------------------------
#define GEMM_ITERS (F_SZ / 16)

__global__ __launch_bounds__(256, 1)
void gemm_tf32_kernel(const float* __restrict__ A, const float* __restrict__ W)
{
    __shared__ float As[2][128][20];   // [plane][m][k(16)+pad4]
    __shared__ float Bs[2][16][136];   // [plane][k][n(128)+pad8]

    const int tid  = threadIdx.x;
    const int lane = tid & 31;
    const int warp = tid >> 5;
    const int wm = warp & 1;          // 0..1
    const int wn = warp >> 1;         // 0..3
    const int bx = blockIdx.x;        // n block 0..7
    const int by = blockIdx.y;        // m block 0..31

    // A global loader mapping: rows am, am+64; cols aq..aq+3 within k-chunk
    const int am = tid >> 2;          // 0..63
    const int aq = (tid & 3) * 4;     // 0,4,8,12
    const float* Ap = A + (size_t)(by * 128 + am) * F_SZ + aq;

    // B global loader mapping: 4 consecutive n at bn, f rows bf and bf+8
    const int bn = (tid & 31) * 4;    // 0..124
    const int bf = tid >> 5;          // 0..7
    const int ng = bx * 128 + bn;
    const float* Bp = W + (size_t)(ng >> 4) * (F_SZ * 16) + (ng & 15);

    float acc[4][4][4];
#pragma unroll
    for (int i = 0; i < 4; i++)
#pragma unroll
        for (int j = 0; j < 4; j++)
#pragma unroll
            for (int r = 0; r < 4; r++) acc[i][j][r] = 0.0f;

    float4 pa0, pa1, pb0, pb1;
    // prefetch iter 0
    pa0 = *(const float4*)(Ap);
    pa1 = *(const float4*)(Ap + (size_t)64 * F_SZ);
    pb0 = *(const float4*)(Bp + (size_t)bf * 16);
    pb1 = *(const float4*)(Bp + (size_t)(bf + 8) * 16);

    for (int it = 0; it < GEMM_ITERS; ++it) {
        __syncthreads();
        // split + store A (hi/lo planes)
        {
            float4 h, l;
            h.x = tf32_rna(pa0.x); l.x = tf32_rna(pa0.x - h.x);
            h.y = tf32_rna(pa0.y); l.y = tf32_rna(pa0.y - h.y);
            h.z = tf32_rna(pa0.z); l.z = tf32_rna(pa0.z - h.z);
            h.w = tf32_rna(pa0.w); l.w = tf32_rna(pa0.w - h.w);
            *(float4*)&As[0][am][aq] = h;
            *(float4*)&As[1][am][aq] = l;
            h.x = tf32_rna(pa1.x); l.x = tf32_rna(pa1.x - h.x);
            h.y = tf32_rna(pa1.y); l.y = tf32_rna(pa1.y - h.y);
            h.z = tf32_rna(pa1.z); l.z = tf32_rna(pa1.z - h.z);
            h.w = tf32_rna(pa1.w); l.w = tf32_rna(pa1.w - h.w);
            *(float4*)&As[0][am + 64][aq] = h;
            *(float4*)&As[1][am + 64][aq] = l;
        }
        // split + store B
        {
            float4 h, l;
            h.x = tf32_rna(pb0.x); l.x = tf32_rna(pb0.x - h.x);
            h.y = tf32_rna(pb0.y); l.y = tf32_rna(pb0.y - h.y);
            h.z = tf32_rna(pb0.z); l.z = tf32_rna(pb0.z - h.z);
            h.w = tf32_rna(pb0.w); l.w = tf32_rna(pb0.w - h.w);
            *(float4*)&Bs[0][bf][bn] = h;
            *(float4*)&Bs[1][bf][bn] = l;
            h.x = tf32_rna(pb1.x); l.x = tf32_rna(pb1.x - h.x);
            h.y = tf32_rna(pb1.y); l.y = tf32_rna(pb1.y - h.y);
            h.z = tf32_rna(pb1.z); l.z = tf32_rna(pb1.z - h.z);
            h.w = tf32_rna(pb1.w); l.w = tf32_rna(pb1.w - h.w);
            *(float4*)&Bs[0][bf + 8][bn] = h;
            *(float4*)&Bs[1][bf + 8][bn] = l;
        }
        __syncthreads();

        if (it + 1 < GEMM_ITERS) {
            const int k0 = (it + 1) * 16;
            pa0 = *(const float4*)(Ap + k0);
            pa1 = *(const float4*)(Ap + (size_t)64 * F_SZ + k0);
            pb0 = *(const float4*)(Bp + (size_t)(k0 + bf) * 16);
            pb1 = *(const float4*)(Bp + (size_t)(k0 + bf + 8) * 16);
        }

#pragma unroll
        for (int ks = 0; ks < 2; ++ks) {
            uint32_t ah[4][4], al[4][4];
            uint32_t bh[4][2], bl[4][2];
            const int ar = (lane >> 2);
            const int ac = ks * 8 + (lane & 3);
#pragma unroll
            for (int mt = 0; mt < 4; ++mt) {
                const int row = wm * 64 + mt * 16 + ar;
                ah[mt][0] = __float_as_uint(As[0][row][ac]);
                ah[mt][1] = __float_as_uint(As[0][row + 8][ac]);
                ah[mt][2] = __float_as_uint(As[0][row][ac + 4]);
                ah[mt][3] = __float_as_uint(As[0][row + 8][ac + 4]);
                al[mt][0] = __float_as_uint(As[1][row][ac]);
                al[mt][1] = __float_as_uint(As[1][row + 8][ac]);
                al[mt][2] = __float_as_uint(As[1][row][ac + 4]);
                al[mt][3] = __float_as_uint(As[1][row + 8][ac + 4]);
            }
            const int bk = ks * 8 + (lane & 3);
            const int bcol = wn * 32 + (lane >> 2);
#pragma unroll
            for (int nt = 0; nt < 4; ++nt) {
                const int n = bcol + nt * 8;
                bh[nt][0] = __float_as_uint(Bs[0][bk][n]);
                bh[nt][1] = __float_as_uint(Bs[0][bk + 4][n]);
                bl[nt][0] = __float_as_uint(Bs[1][bk][n]);
                bl[nt][1] = __float_as_uint(Bs[1][bk + 4][n]);
            }
#pragma unroll
            for (int mt = 0; mt < 4; ++mt)
#pragma unroll
                for (int nt = 0; nt < 4; ++nt) {
                    mma_tf32(acc[mt][nt], ah[mt][0], ah[mt][1], ah[mt][2], ah[mt][3],
                             bh[nt][0], bh[nt][1]);
                    mma_tf32(acc[mt][nt], ah[mt][0], ah[mt][1], ah[mt][2], ah[mt][3],
                             bl[nt][0], bl[nt][1]);
                    mma_tf32(acc[mt][nt], al[mt][0], al[mt][1], al[mt][2], al[mt][3],
                             bh[nt][0], bh[nt][1]);
                }
        }
    }

    // epilogue: write to g_theta
    const int mbase = by * 128 + wm * 64 + (lane >> 2);
    const int nbase = bx * 128 + wn * 32 + (lane & 3) * 2;
#pragma unroll
    for (int mt = 0; mt < 4; ++mt) {
#pragma unroll
        for (int nt = 0; nt < 4; ++nt) {
            const int m = mbase + mt * 16;
            const int n = nbase + nt * 8;
            float* p = g_theta + (size_t)m * N_SZ + n;
            p[0] = acc[mt][nt][0];
            p[1] = acc[mt][nt][1];
            p[(size_t)8 * N_SZ]     = acc[mt][nt][2];
            p[(size_t)8 * N_SZ + 1] = acc[mt][nt][3];
        }
    }
}

// ---------------------------------------------------------------------------
// Kernel 2: per-box epilogue (unchanged)
// ---------------------------------------------------------------------------
__global__ __launch_bounds__(64)
void box_kernel(const float* __restrict__ bp, const float* __restrict__ Wprob,
                const float* __restrict__ bprob, const float* __restrict__ Wbox,
                float* __restrict__ out)
{
    const int b = blockIdx.x;
    const int k = threadIdx.x;

    const float* th  = g_theta + (size_t)b * N_SZ + k * 16;
    const float* bpk = bp + k * 16;

    float z[8], Zb[8];
#pragma unroll
    for (int d = 0; d < 8; d++) {
        float zv = th[d] + bpk[d];
        float u  = th[8 + d] + bpk[8 + d];
        z[d]  = zv;
        Zb[d] = zv + softplus_f(u);
    }

    const float* wp = Wprob + k * 16;
    float logit = bprob[k];
#pragma unroll
    for (int d = 0; d < 8; d++)
        logit += z[d] * wp[d] + Zb[d] * wp[8 + d];
    float p = sigmoid_f(logit);
    out[OUT_CONCEPT_OFF + b * K_SZ + k] = p;

    float lv2 = 0.0f;
#pragma unroll
    for (int d = 0; d < 8; d++)
        lv2 += log2_side(z[d], Zb[d]);
    g_lvbox2[b * K_SZ + k] = lv2;

    float* gz = g_z  + (size_t)b * (K_SZ * D_SZ) + k * 8;
    float* gZ = g_Zc + (size_t)b * (K_SZ * D_SZ) + k * 8;
#pragma unroll
    for (int d = 0; d < 8; d++) { gz[d] = z[d]; gZ[d] = Zb[d]; }

    const float* wb = Wbox + k * 16;
    float c = 0.0f;
#pragma unroll
    for (int d = 0; d < 8; d++)
        c += z[d] * wb[d] + Zb[d] * wb[8 + d];
    c *= p;

    __shared__ float red[64];
    red[k] = c;
    __syncthreads();
    if (k == 0) {
        float s = 0.0f;
        for (int i = 0; i < 64; i++) s += red[i];
        g_boxsum[b] = s;
    }
}

// ---------------------------------------------------------------------------
// Kernel 3: pairwise intersections (unchanged)
// ---------------------------------------------------------------------------
__global__ __launch_bounds__(256)
void pair_kernel(const float* __restrict__ Wrel, const float* __restrict__ bbox,
                 const float* __restrict__ brel, float* __restrict__ out)
{
    const int b = blockIdx.x;
    const int tid = threadIdx.x;

    __shared__ __align__(16) float sz[K_SZ * D_SZ];
    __shared__ __align__(16) float sZ[K_SZ * D_SZ];
    __shared__ __align__(16) float slv[K_SZ];
    __shared__ __align__(16) float sw[K_SZ * K_SZ];
    __shared__ __align__(16) float sc[K_SZ * K_SZ];
    __shared__ float rr[8];

    const float* gz = g_z  + (size_t)b * (K_SZ * D_SZ);
    const float* gZ = g_Zc + (size_t)b * (K_SZ * D_SZ);
    for (int i = tid; i < K_SZ * D_SZ; i += 256) { sz[i] = gz[i]; sZ[i] = gZ[i]; }
    if (tid < K_SZ) slv[tid] = g_lvbox2[b * K_SZ + tid];
    for (int i = tid; i < K_SZ * K_SZ; i += 256) sw[i] = Wrel[i];
    __syncthreads();

    for (int p = tid; p < NPAIR; p += 256) {
        int i = (int)((sqrtf(8.0f * (float)p + 1.0f) - 1.0f) * 0.5f);
        while ((i + 1) * (i + 2) / 2 <= p) ++i;
        while (i * (i + 1) / 2 > p) --i;
        int j = p - i * (i + 1) / 2;

        const float* zi = sz + i * 8;
        const float* zj = sz + j * 8;
        const float* Zi = sZ + i * 8;
        const float* Zj = sZ + j * 8;

        float lv2 = 0.0f;
#pragma unroll
        for (int d = 0; d < 8; d++) {
            float a = zi[d], c = zj[d];
            float zint = fmaxf(a, c)
                       + 0.1f * __logf(1.0f + __expf(-10.0f * fabsf(a - c)));
            float A2 = Zi[d], C2 = Zj[d];
            float Zint = fminf(A2, C2)
                       - 0.1f * __logf(1.0f + __expf(-10.0f * fabsf(A2 - C2)));
            lv2 += log2_side(zint, Zint);
        }

        float cij = exp2f(lv2 - slv[j]);
        cij = fminf(fmaxf(cij, 1e-6f), 1.0f - 1e-6f);
        float cji = exp2f(lv2 - slv[i]);
        cji = fminf(fmaxf(cji, 1e-6f), 1.0f - 1e-6f);
        sc[i * K_SZ + j] = cij;
        sc[j * K_SZ + i] = cji;
    }
    __syncthreads();

    float acc = 0.0f;
    float4* condout = (float4*)(out + OUT_COND_OFF + (size_t)b * (K_SZ * K_SZ));
    for (int q = tid; q < (K_SZ * K_SZ) / 4; q += 256) {
        float4 v = *(const float4*)&sc[q * 4];
        float4 w = *(const float4*)&sw[q * 4];
        condout[q] = v;
        acc += v.x * w.x + v.y * w.y + v.z * w.z + v.w * w.w;
    }

#pragma unroll
    for (int off = 16; off > 0; off >>= 1)
        acc += __shfl_down_sync(0xffffffffu, acc, off);
    if ((tid & 31) == 0) rr[tid >> 5] = acc;
    __syncthreads();
    if (tid == 0) {
        float s = 0.0f;
        for (int w = 0; w < 8; w++) s += rr[w];
        float logit = g_boxsum[b] + bbox[0] + s + brel[0];
        out[b] = sigmoid_f(logit);
    }
}

// ---------------------------------------------------------------------------
extern "C" void kernel_launch(void* const* d_in, const int* in_sizes, int n_in,
                              void* d_out, int out_size)
{
    const float* features = (const float*)d_in[0];
    const float* Wp       = (const float*)d_in[1];
    const float* bp       = (const float*)d_in[2];
    const float* Wprob    = (const float*)d_in[3];
    const float* bprob    = (const float*)d_in[4];
    const float* Wbox     = (const float*)d_in[5];
    const float* bbox     = (const float*)d_in[6];
    const float* Wrel     = (const float*)d_in[7];
    const float* brel     = (const float*)d_in[8];
    float* out = (float*)d_out;

    dim3 g1(N_SZ / 128, B_SZ / 128);   // (8, 32)
    gemm_tf32_kernel<<<g1, 256>>>(features, Wp);
    box_kernel<<<B_SZ, 64>>>(bp, Wprob, bprob, Wbox, out);
    pair_kernel<<<B_SZ, 256>>>(Wrel, bbox, brel, out);
}

// round 7
// speedup vs baseline: 1.6662x; 1.3933x over previous
#include <cuda_runtime.h>
#include <cuda_bf16.h>
#include <math.h>
#include <stdint.h>

// ---------------------------------------------------------------------------
// Problem constants
// ---------------------------------------------------------------------------
#define B_SZ 4096
#define K_SZ 64
#define D_SZ 8
#define F_SZ 2048
#define N_SZ 1024
#define NPAIR (K_SZ * (K_SZ + 1) / 2)

#define OUT_CONCEPT_OFF (B_SZ)
#define OUT_COND_OFF (B_SZ + B_SZ * K_SZ)

// GEMM tiling: block 128x128, BK=32 (16 bf16x2 words), 2-stage smem pipeline
#define GITERS (F_SZ / 32)        // 64
#define ASTRIDE 20                // words per A row (16 + pad 4) -> conflict-free
#define BSTRIDE 136               // words per B row (128 + pad 8) -> conflict-free
#define A_PLANE_W (128 * ASTRIDE) // 2560
#define B_PLANE_W (16 * BSTRIDE)  // 2176
#define STAGE_W (2 * A_PLANE_W + 2 * B_PLANE_W)  // 9472 words
#define SMEM_BYTES (2 * STAGE_W * 4)             // 75776 B

// ---------------------------------------------------------------------------
// Scratch (__device__ globals; no allocation)
// ---------------------------------------------------------------------------
__device__ float g_theta[(size_t)B_SZ * N_SZ];
__device__ float g_z[(size_t)B_SZ * K_SZ * D_SZ];
__device__ float g_Zc[(size_t)B_SZ * K_SZ * D_SZ];
__device__ float g_lvbox2[B_SZ * K_SZ];
__device__ float g_boxsum[B_SZ];

// pre-split bf16 operands, packed as bf16x2 words
// A planes: [4096 rows][1024 kwords] ; word kw = (f=2kw, f=2kw+1)
__device__ uint32_t g_AhiW[(size_t)B_SZ * (F_SZ / 2)];
__device__ uint32_t g_AloW[(size_t)B_SZ * (F_SZ / 2)];
// B planes: [1024 fwords][1024 n] ; word(fw,n) = (bf16(f=2fw,n), bf16(f=2fw+1,n))
__device__ uint32_t g_BhiW[(size_t)(F_SZ / 2) * N_SZ];
__device__ uint32_t g_BloW[(size_t)(F_SZ / 2) * N_SZ];

// ---------------------------------------------------------------------------
// math helpers
// ---------------------------------------------------------------------------
__device__ __forceinline__ float softplus_f(float x) {
    float e = __expf(-fabsf(x));
    return fmaxf(x, 0.0f) + __logf(1.0f + e);
}
__device__ __forceinline__ float log2_side(float z, float Z) {
    float x = 2.0f * (Z - z);
    float sp = fmaxf(x, 0.0f) + __logf(1.0f + __expf(-fabsf(x)));
    float side = 0.5f * sp;
    return __log2f(fmaxf(side, 1e-23f));
}
__device__ __forceinline__ float sigmoid_f(float x) {
    return 1.0f / (1.0f + __expf(-x));
}

__device__ __forceinline__ void mma_bf16(float* c, const uint32_t* a, const uint32_t* b) {
    asm volatile(
        "mma.sync.aligned.m16n8k16.row.col.f32.bf16.bf16.f32 "
        "{%0,%1,%2,%3}, {%4,%5,%6,%7}, {%8,%9}, {%0,%1,%2,%3};"
        : "+f"(c[0]), "+f"(c[1]), "+f"(c[2]), "+f"(c[3])
        : "r"(a[0]), "r"(a[1]), "r"(a[2]), "r"(a[3]), "r"(b[0]), "r"(b[1]));
}

__device__ __forceinline__ uint32_t pack_hi(float x, float y) {
    __nv_bfloat162 v = __halves2bfloat162(__float2bfloat16(x), __float2bfloat16(y));
    return *(uint32_t*)&v;
}
__device__ __forceinline__ uint32_t pack_lo(float x, float y) {
    __nv_bfloat16 hx = __float2bfloat16(x);
    __nv_bfloat16 hy = __float2bfloat16(y);
    __nv_bfloat162 v = __halves2bfloat162(__float2bfloat16(x - __bfloat162float(hx)),
                                          __float2bfloat16(y - __bfloat162float(hy)));
    return *(uint32_t*)&v;
}

// ---------------------------------------------------------------------------
// Convert A: fp32 [4096,2048] -> packed bf16x2 hi/lo word arrays
// ---------------------------------------------------------------------------
__global__ __launch_bounds__(256)
void convert_A(const float* __restrict__ A)
{
    int gid = blockIdx.x * 256 + threadIdx.x;       // one float4 each
    float4 v = *(const float4*)(A + (size_t)gid * 4);
    uint2 hi = make_uint2(pack_hi(v.x, v.y), pack_hi(v.z, v.w));
    uint2 lo = make_uint2(pack_lo(v.x, v.y), pack_lo(v.z, v.w));
    *(uint2*)(g_AhiW + (size_t)gid * 2) = hi;
    *(uint2*)(g_AloW + (size_t)gid * 2) = lo;
}

// ---------------------------------------------------------------------------
// Convert B: Wp[k][f][d] (n = k*16+d) -> word(fw, n) arrays
// ---------------------------------------------------------------------------
__global__ __launch_bounds__(256)
void convert_B(const float* __restrict__ Wp)
{
    int gid = blockIdx.x * 256 + threadIdx.x;       // 1M threads
    int fw = gid >> 10;            // 0..1023
    int n  = gid & 1023;
    int k = n >> 4, d = n & 15;
    const float* base = Wp + (size_t)k * (F_SZ * 16) + d;
    float x = base[(size_t)(2 * fw) * 16];
    float y = base[(size_t)(2 * fw + 1) * 16];
    g_BhiW[gid] = pack_hi(x, y);
    g_BloW[gid] = pack_lo(x, y);
}

// ---------------------------------------------------------------------------
// bf16 3-pass tensor-core GEMM (legacy mma.sync path, portable PTX).
// C[4096,1024] = A x W. Block 128x128, 8 warps (2m x 4n), warp tile 64x32.
// BK=32, double-buffered smem, one __syncthreads per iter.
// ---------------------------------------------------------------------------
__global__ __launch_bounds__(256, 1)
void gemm_bf16()
{
    extern __shared__ uint32_t sm[];
#define AS(s,p,m,kw) sm[(s) * STAGE_W + (p) * A_PLANE_W + (m) * ASTRIDE + (kw)]
#define BS(s,p,kw,n) sm[(s) * STAGE_W + 2 * A_PLANE_W + (p) * B_PLANE_W + (kw) * BSTRIDE + (n)]

    const int tid  = threadIdx.x;
    const int lane = tid & 31;
    const int warp = tid >> 5;
    const int wm = warp & 1;
    const int wn = warp >> 1;
    const int bx = blockIdx.x;   // 0..7
    const int by = blockIdx.y;   // 0..31

    // global load mapping
    const int am  = tid >> 1;            // 0..127
    const int akw = (tid & 1) * 8;       // 0 or 8
    const uint32_t* ApH = g_AhiW + (size_t)(by * 128 + am) * (F_SZ / 2) + akw;
    const uint32_t* ApL = g_AloW + (size_t)(by * 128 + am) * (F_SZ / 2) + akw;
    const int bfw = tid >> 4;            // 0..15
    const int bnf = (tid & 15) * 8;      // 0..120
    const uint32_t* BpH = g_BhiW + (size_t)bfw * N_SZ + bx * 128 + bnf;
    const uint32_t* BpL = g_BloW + (size_t)bfw * N_SZ + bx * 128 + bnf;

    float acc[4][4][4];
#pragma unroll
    for (int i = 0; i < 4; i++)
#pragma unroll
        for (int j = 0; j < 4; j++)
#pragma unroll
            for (int r = 0; r < 4; r++) acc[i][j][r] = 0.0f;

    uint4 rah0, rah1, ral0, ral1, rbh0, rbh1, rbl0, rbl1;

    // prime stage 0
    rah0 = *(const uint4*)(ApH);      rah1 = *(const uint4*)(ApH + 4);
    ral0 = *(const uint4*)(ApL);      ral1 = *(const uint4*)(ApL + 4);
    rbh0 = *(const uint4*)(BpH);      rbh1 = *(const uint4*)(BpH + 4);
    rbl0 = *(const uint4*)(BpL);      rbl1 = *(const uint4*)(BpL + 4);
    *(uint4*)&AS(0, 0, am, akw)     = rah0;
    *(uint4*)&AS(0, 0, am, akw + 4) = rah1;
    *(uint4*)&AS(0, 1, am, akw)     = ral0;
    *(uint4*)&AS(0, 1, am, akw + 4) = ral1;
    *(uint4*)&BS(0, 0, bfw, bnf)     = rbh0;
    *(uint4*)&BS(0, 0, bfw, bnf + 4) = rbh1;
    *(uint4*)&BS(0, 1, bfw, bnf)     = rbl0;
    *(uint4*)&BS(0, 1, bfw, bnf + 4) = rbl1;
    __syncthreads();

    const int ar = lane >> 2;       // A frag row within 16
    const int aq = lane & 3;        // A frag kword
    const int bq = lane & 3;        // B frag kword
    const int bc = lane >> 2;       // B frag col within 8

    for (int it = 0; it < GITERS; ++it) {
        const int s = it & 1;

        if (it + 1 < GITERS) {
            const int kb = (it + 1) * 16;   // kword base
            rah0 = *(const uint4*)(ApH + kb);
            rah1 = *(const uint4*)(ApH + kb + 4);
            ral0 = *(const uint4*)(ApL + kb);
            ral1 = *(const uint4*)(ApL + kb + 4);
            rbh0 = *(const uint4*)(BpH + (size_t)kb * N_SZ);
            rbh1 = *(const uint4*)(BpH + (size_t)kb * N_SZ + 4);
            rbl0 = *(const uint4*)(BpL + (size_t)kb * N_SZ);
            rbl1 = *(const uint4*)(BpL + (size_t)kb * N_SZ + 4);
        }

#pragma unroll
        for (int ks = 0; ks < 2; ++ks) {
            uint32_t ah[4][4], al[4][4], bh[4][2], bl[4][2];
            const int kwb = ks * 8;
#pragma unroll
            for (int mt = 0; mt < 4; ++mt) {
                const int row = wm * 64 + mt * 16 + ar;
                ah[mt][0] = AS(s, 0, row,     kwb + aq);
                ah[mt][1] = AS(s, 0, row + 8, kwb + aq);
                ah[mt][2] = AS(s, 0, row,     kwb + aq + 4);
                ah[mt][3] = AS(s, 0, row + 8, kwb + aq + 4);
                al[mt][0] = AS(s, 1, row,     kwb + aq);
                al[mt][1] = AS(s, 1, row + 8, kwb + aq);
                al[mt][2] = AS(s, 1, row,     kwb + aq + 4);
                al[mt][3] = AS(s, 1, row + 8, kwb + aq + 4);
            }
#pragma unroll
            for (int nt = 0; nt < 4; ++nt) {
                const int n = wn * 32 + nt * 8 + bc;
                bh[nt][0] = BS(s, 0, kwb + bq,     n);
                bh[nt][1] = BS(s, 0, kwb + bq + 4, n);
                bl[nt][0] = BS(s, 1, kwb + bq,     n);
                bl[nt][1] = BS(s, 1, kwb + bq + 4, n);
            }
#pragma unroll
            for (int mt = 0; mt < 4; ++mt)
#pragma unroll
                for (int nt = 0; nt < 4; ++nt) {
                    mma_bf16(acc[mt][nt], ah[mt], bh[nt]);
                    mma_bf16(acc[mt][nt], ah[mt], bl[nt]);
                    mma_bf16(acc[mt][nt], al[mt], bh[nt]);
                }
        }

        if (it + 1 < GITERS) {
            const int ns = s ^ 1;
            *(uint4*)&AS(ns, 0, am, akw)     = rah0;
            *(uint4*)&AS(ns, 0, am, akw + 4) = rah1;
            *(uint4*)&AS(ns, 1, am, akw)     = ral0;
            *(uint4*)&AS(ns, 1, am, akw + 4) = ral1;
            *(uint4*)&BS(ns, 0, bfw, bnf)     = rbh0;
            *(uint4*)&BS(ns, 0, bfw, bnf + 4) = rbh1;
            *(uint4*)&BS(ns, 1, bfw, bnf)     = rbl0;
            *(uint4*)&BS(ns, 1, bfw, bnf + 4) = rbl1;
            __syncthreads();
        }
    }

    // epilogue
    const int mbase = by * 128 + wm * 64 + (lane >> 2);
    const int nbase = bx * 128 + wn * 32 + (lane & 3) * 2;
#pragma unroll
    for (int mt = 0; mt < 4; ++mt) {
#pragma unroll
        for (int nt = 0; nt < 4; ++nt) {
            const int m = mbase + mt * 16;
            const int n = nbase + nt * 8;
            float* p = g_theta + (size_t)m * N_SZ + n;
            p[0] = acc[mt][nt][0];
            p[1] = acc[mt][nt][1];
            p[(size_t)8 * N_SZ]     = acc[mt][nt][2];
            p[(size_t)8 * N_SZ + 1] = acc[mt][nt][3];
        }
    }
#undef AS
#undef BS
}

// ---------------------------------------------------------------------------
// Per-box epilogue: 256 threads, 4 batches per block
// ---------------------------------------------------------------------------
__global__ __launch_bounds__(256)
void box_kernel(const float* __restrict__ bp, const float* __restrict__ Wprob,
                const float* __restrict__ bprob, const float* __restrict__ Wbox,
                float* __restrict__ out)
{
    const int bl = threadIdx.x >> 6;             // 0..3
    const int k  = threadIdx.x & 63;
    const int b  = blockIdx.x * 4 + bl;

    const float* th  = g_theta + (size_t)b * N_SZ + k * 16;
    const float* bpk = bp + k * 16;

    float z[8], Zb[8];
#pragma unroll
    for (int d = 0; d < 8; d++) {
        float zv = th[d] + bpk[d];
        float u  = th[8 + d] + bpk[8 + d];
        z[d]  = zv;
        Zb[d] = zv + softplus_f(u);
    }

    const float* wp = Wprob + k * 16;
    float logit = bprob[k];
#pragma unroll
    for (int d = 0; d < 8; d++)
        logit += z[d] * wp[d] + Zb[d] * wp[8 + d];
    float p = sigmoid_f(logit);
    out[OUT_CONCEPT_OFF + b * K_SZ + k] = p;

    float lv2 = 0.0f;
#pragma unroll
    for (int d = 0; d < 8; d++)
        lv2 += log2_side(z[d], Zb[d]);
    g_lvbox2[b * K_SZ + k] = lv2;

    float* gz = g_z  + (size_t)b * (K_SZ * D_SZ) + k * 8;
    float* gZ = g_Zc + (size_t)b * (K_SZ * D_SZ) + k * 8;
#pragma unroll
    for (int d = 0; d < 8; d++) { gz[d] = z[d]; gZ[d] = Zb[d]; }

    const float* wb = Wbox + k * 16;
    float c = 0.0f;
#pragma unroll
    for (int d = 0; d < 8; d++)
        c += z[d] * wb[d] + Zb[d] * wb[8 + d];
    c *= p;

    // reduce 64 values within each b-group (2 warps)
    __shared__ float red[4][64];
    red[bl][k] = c;
    __syncthreads();
    if (k == 0) {
        float s = 0.0f;
#pragma unroll
        for (int i = 0; i < 64; i++) s += red[bl][i];
        g_boxsum[b] = s;
    }
}

// ---------------------------------------------------------------------------
// Pairwise intersections (unchanged)
// ---------------------------------------------------------------------------
__global__ __launch_bounds__(256)
void pair_kernel(const float* __restrict__ Wrel, const float* __restrict__ bbox,
                 const float* __restrict__ brel, float* __restrict__ out)
{
    const int b = blockIdx.x;
    const int tid = threadIdx.x;

    __shared__ __align__(16) float sz[K_SZ * D_SZ];
    __shared__ __align__(16) float sZ[K_SZ * D_SZ];
    __shared__ __align__(16) float slv[K_SZ];
    __shared__ __align__(16) float sw[K_SZ * K_SZ];
    __shared__ __align__(16) float sc[K_SZ * K_SZ];
    __shared__ float rr[8];

    const float* gz = g_z  + (size_t)b * (K_SZ * D_SZ);
    const float* gZ = g_Zc + (size_t)b * (K_SZ * D_SZ);
    for (int i = tid; i < K_SZ * D_SZ; i += 256) { sz[i] = gz[i]; sZ[i] = gZ[i]; }
    if (tid < K_SZ) slv[tid] = g_lvbox2[b * K_SZ + tid];
    for (int i = tid; i < K_SZ * K_SZ; i += 256) sw[i] = Wrel[i];
    __syncthreads();

    for (int p = tid; p < NPAIR; p += 256) {
        int i = (int)((sqrtf(8.0f * (float)p + 1.0f) - 1.0f) * 0.5f);
        while ((i + 1) * (i + 2) / 2 <= p) ++i;
        while (i * (i + 1) / 2 > p) --i;
        int j = p - i * (i + 1) / 2;

        const float* zi = sz + i * 8;
        const float* zj = sz + j * 8;
        const float* Zi = sZ + i * 8;
        const float* Zj = sZ + j * 8;

        float lv2 = 0.0f;
#pragma unroll
        for (int d = 0; d < 8; d++) {
            float a = zi[d], c = zj[d];
            float zint = fmaxf(a, c)
                       + 0.1f * __logf(1.0f + __expf(-10.0f * fabsf(a - c)));
            float A2 = Zi[d], C2 = Zj[d];
            float Zint = fminf(A2, C2)
                       - 0.1f * __logf(1.0f + __expf(-10.0f * fabsf(A2 - C2)));
            lv2 += log2_side(zint, Zint);
        }

        float cij = exp2f(lv2 - slv[j]);
        cij = fminf(fmaxf(cij, 1e-6f), 1.0f - 1e-6f);
        float cji = exp2f(lv2 - slv[i]);
        cji = fminf(fmaxf(cji, 1e-6f), 1.0f - 1e-6f);
        sc[i * K_SZ + j] = cij;
        sc[j * K_SZ + i] = cji;
    }
    __syncthreads();

    float acc = 0.0f;
    float4* condout = (float4*)(out + OUT_COND_OFF + (size_t)b * (K_SZ * K_SZ));
    for (int q = tid; q < (K_SZ * K_SZ) / 4; q += 256) {
        float4 v = *(const float4*)&sc[q * 4];
        float4 w = *(const float4*)&sw[q * 4];
        condout[q] = v;
        acc += v.x * w.x + v.y * w.y + v.z * w.z + v.w * w.w;
    }

#pragma unroll
    for (int off = 16; off > 0; off >>= 1)
        acc += __shfl_down_sync(0xffffffffu, acc, off);
    if ((tid & 31) == 0) rr[tid >> 5] = acc;
    __syncthreads();
    if (tid == 0) {
        float s = 0.0f;
        for (int w = 0; w < 8; w++) s += rr[w];
        float logit = g_boxsum[b] + bbox[0] + s + brel[0];
        out[b] = sigmoid_f(logit);
    }
}

// ---------------------------------------------------------------------------
extern "C" void kernel_launch(void* const* d_in, const int* in_sizes, int n_in,
                              void* d_out, int out_size)
{
    const float* features = (const float*)d_in[0];
    const float* Wp       = (const float*)d_in[1];
    const float* bp       = (const float*)d_in[2];
    const float* Wprob    = (const float*)d_in[3];
    const float* bprob    = (const float*)d_in[4];
    const float* Wbox     = (const float*)d_in[5];
    const float* bbox     = (const float*)d_in[6];
    const float* Wrel     = (const float*)d_in[7];
    const float* brel     = (const float*)d_in[8];
    float* out = (float*)d_out;

    cudaFuncSetAttribute(gemm_bf16, cudaFuncAttributeMaxDynamicSharedMemorySize, SMEM_BYTES);

    convert_A<<<(B_SZ * F_SZ / 4) / 256, 256>>>(features);   // 8192 blocks
    convert_B<<<(F_SZ / 2) * N_SZ / 256, 256>>>(Wp);         // 4096 blocks
    gemm_bf16<<<dim3(8, 32), 256, SMEM_BYTES>>>();
    box_kernel<<<B_SZ / 4, 256>>>(bp, Wprob, bprob, Wbox, out);
    pair_kernel<<<B_SZ, 256>>>(Wrel, bbox, brel, out);
}

// round 8
// speedup vs baseline: 1.9111x; 1.1470x over previous
#include <cuda_runtime.h>
#include <cuda_bf16.h>
#include <math.h>
#include <stdint.h>

// ---------------------------------------------------------------------------
// Problem constants
// ---------------------------------------------------------------------------
#define B_SZ 4096
#define K_SZ 64
#define D_SZ 8
#define F_SZ 2048
#define N_SZ 1024
#define NPAIR (K_SZ * (K_SZ + 1) / 2)

#define OUT_CONCEPT_OFF (B_SZ)
#define OUT_COND_OFF (B_SZ + B_SZ * K_SZ)

// GEMM tiling: block 128x128, BK=32 (16 bf16x2 words), 2-stage smem pipeline
#define GITERS (F_SZ / 32)        // 64
#define ASTRIDE 20
#define BSTRIDE 136
#define A_PLANE_W (128 * ASTRIDE)
#define B_PLANE_W (16 * BSTRIDE)
#define STAGE_W (2 * A_PLANE_W + 2 * B_PLANE_W)
#define SMEM_BYTES (2 * STAGE_W * 4)

// ---------------------------------------------------------------------------
// Scratch (__device__ globals; no allocation)
// ---------------------------------------------------------------------------
__device__ __align__(256) float g_theta[(size_t)B_SZ * N_SZ];

// pre-split bf16 operands, packed as bf16x2 words
__device__ uint32_t g_AhiW[(size_t)B_SZ * (F_SZ / 2)];
__device__ uint32_t g_AloW[(size_t)B_SZ * (F_SZ / 2)];
__device__ uint32_t g_BhiW[(size_t)(F_SZ / 2) * N_SZ];
__device__ uint32_t g_BloW[(size_t)(F_SZ / 2) * N_SZ];

// ---------------------------------------------------------------------------
// math helpers
// ---------------------------------------------------------------------------
__device__ __forceinline__ float softplus_f(float x) {
    float e = __expf(-fabsf(x));
    return fmaxf(x, 0.0f) + __logf(1.0f + e);
}
__device__ __forceinline__ float sigmoid_f(float x) {
    return 1.0f / (1.0f + __expf(-x));
}

__device__ __forceinline__ void mma_bf16(float* c, const uint32_t* a, const uint32_t* b) {
    asm volatile(
        "mma.sync.aligned.m16n8k16.row.col.f32.bf16.bf16.f32 "
        "{%0,%1,%2,%3}, {%4,%5,%6,%7}, {%8,%9}, {%0,%1,%2,%3};"
        : "+f"(c[0]), "+f"(c[1]), "+f"(c[2]), "+f"(c[3])
        : "r"(a[0]), "r"(a[1]), "r"(a[2]), "r"(a[3]), "r"(b[0]), "r"(b[1]));
}

__device__ __forceinline__ uint32_t pack_hi(float x, float y) {
    __nv_bfloat162 v = __halves2bfloat162(__float2bfloat16(x), __float2bfloat16(y));
    return *(uint32_t*)&v;
}
__device__ __forceinline__ uint32_t pack_lo(float x, float y) {
    __nv_bfloat16 hx = __float2bfloat16(x);
    __nv_bfloat16 hy = __float2bfloat16(y);
    __nv_bfloat162 v = __halves2bfloat162(__float2bfloat16(x - __bfloat162float(hx)),
                                          __float2bfloat16(y - __bfloat162float(hy)));
    return *(uint32_t*)&v;
}

// ---------------------------------------------------------------------------
// Convert A: fp32 [4096,2048] -> packed bf16x2 hi/lo word arrays
// ---------------------------------------------------------------------------
__global__ __launch_bounds__(256)
void convert_A(const float* __restrict__ A)
{
    int gid = blockIdx.x * 256 + threadIdx.x;
    float4 v = *(const float4*)(A + (size_t)gid * 4);
    uint2 hi = make_uint2(pack_hi(v.x, v.y), pack_hi(v.z, v.w));
    uint2 lo = make_uint2(pack_lo(v.x, v.y), pack_lo(v.z, v.w));
    *(uint2*)(g_AhiW + (size_t)gid * 2) = hi;
    *(uint2*)(g_AloW + (size_t)gid * 2) = lo;
}

// ---------------------------------------------------------------------------
// Convert B: Wp[k][f][d] (n = k*16+d) -> word(fw, n) arrays
// ---------------------------------------------------------------------------
__global__ __launch_bounds__(256)
void convert_B(const float* __restrict__ Wp)
{
    int gid = blockIdx.x * 256 + threadIdx.x;
    int fw = gid >> 10;
    int n  = gid & 1023;
    int k = n >> 4, d = n & 15;
    const float* base = Wp + (size_t)k * (F_SZ * 16) + d;
    float x = base[(size_t)(2 * fw) * 16];
    float y = base[(size_t)(2 * fw + 1) * 16];
    g_BhiW[gid] = pack_hi(x, y);
    g_BloW[gid] = pack_lo(x, y);
}

// ---------------------------------------------------------------------------
// bf16 3-pass tensor-core GEMM (unchanged from R7 — passing at ~195us)
// ---------------------------------------------------------------------------
__global__ __launch_bounds__(256, 1)
void gemm_bf16()
{
    extern __shared__ uint32_t sm[];
#define AS(s,p,m,kw) sm[(s) * STAGE_W + (p) * A_PLANE_W + (m) * ASTRIDE + (kw)]
#define BS(s,p,kw,n) sm[(s) * STAGE_W + 2 * A_PLANE_W + (p) * B_PLANE_W + (kw) * BSTRIDE + (n)]

    const int tid  = threadIdx.x;
    const int lane = tid & 31;
    const int warp = tid >> 5;
    const int wm = warp & 1;
    const int wn = warp >> 1;
    const int bx = blockIdx.x;
    const int by = blockIdx.y;

    const int am  = tid >> 1;
    const int akw = (tid & 1) * 8;
    const uint32_t* ApH = g_AhiW + (size_t)(by * 128 + am) * (F_SZ / 2) + akw;
    const uint32_t* ApL = g_AloW + (size_t)(by * 128 + am) * (F_SZ / 2) + akw;
    const int bfw = tid >> 4;
    const int bnf = (tid & 15) * 8;
    const uint32_t* BpH = g_BhiW + (size_t)bfw * N_SZ + bx * 128 + bnf;
    const uint32_t* BpL = g_BloW + (size_t)bfw * N_SZ + bx * 128 + bnf;

    float acc[4][4][4];
#pragma unroll
    for (int i = 0; i < 4; i++)
#pragma unroll
        for (int j = 0; j < 4; j++)
#pragma unroll
            for (int r = 0; r < 4; r++) acc[i][j][r] = 0.0f;

    uint4 rah0, rah1, ral0, ral1, rbh0, rbh1, rbl0, rbl1;

    rah0 = *(const uint4*)(ApH);      rah1 = *(const uint4*)(ApH + 4);
    ral0 = *(const uint4*)(ApL);      ral1 = *(const uint4*)(ApL + 4);
    rbh0 = *(const uint4*)(BpH);      rbh1 = *(const uint4*)(BpH + 4);
    rbl0 = *(const uint4*)(BpL);      rbl1 = *(const uint4*)(BpL + 4);
    *(uint4*)&AS(0, 0, am, akw)     = rah0;
    *(uint4*)&AS(0, 0, am, akw + 4) = rah1;
    *(uint4*)&AS(0, 1, am, akw)     = ral0;
    *(uint4*)&AS(0, 1, am, akw + 4) = ral1;
    *(uint4*)&BS(0, 0, bfw, bnf)     = rbh0;
    *(uint4*)&BS(0, 0, bfw, bnf + 4) = rbh1;
    *(uint4*)&BS(0, 1, bfw, bnf)     = rbl0;
    *(uint4*)&BS(0, 1, bfw, bnf + 4) = rbl1;
    __syncthreads();

    const int ar = lane >> 2;
    const int aq = lane & 3;
    const int bq = lane & 3;
    const int bc = lane >> 2;

    for (int it = 0; it < GITERS; ++it) {
        const int s = it & 1;

        if (it + 1 < GITERS) {
            const int kb = (it + 1) * 16;
            rah0 = *(const uint4*)(ApH + kb);
            rah1 = *(const uint4*)(ApH + kb + 4);
            ral0 = *(const uint4*)(ApL + kb);
            ral1 = *(const uint4*)(ApL + kb + 4);
            rbh0 = *(const uint4*)(BpH + (size_t)kb * N_SZ);
            rbh1 = *(const uint4*)(BpH + (size_t)kb * N_SZ + 4);
            rbl0 = *(const uint4*)(BpL + (size_t)kb * N_SZ);
            rbl1 = *(const uint4*)(BpL + (size_t)kb * N_SZ + 4);
        }

#pragma unroll
        for (int ks = 0; ks < 2; ++ks) {
            uint32_t ah[4][4], al[4][4], bh[4][2], bl[4][2];
            const int kwb = ks * 8;
#pragma unroll
            for (int mt = 0; mt < 4; ++mt) {
                const int row = wm * 64 + mt * 16 + ar;
                ah[mt][0] = AS(s, 0, row,     kwb + aq);
                ah[mt][1] = AS(s, 0, row + 8, kwb + aq);
                ah[mt][2] = AS(s, 0, row,     kwb + aq + 4);
                ah[mt][3] = AS(s, 0, row + 8, kwb + aq + 4);
                al[mt][0] = AS(s, 1, row,     kwb + aq);
                al[mt][1] = AS(s, 1, row + 8, kwb + aq);
                al[mt][2] = AS(s, 1, row,     kwb + aq + 4);
                al[mt][3] = AS(s, 1, row + 8, kwb + aq + 4);
            }
#pragma unroll
            for (int nt = 0; nt < 4; ++nt) {
                const int n = wn * 32 + nt * 8 + bc;
                bh[nt][0] = BS(s, 0, kwb + bq,     n);
                bh[nt][1] = BS(s, 0, kwb + bq + 4, n);
                bl[nt][0] = BS(s, 1, kwb + bq,     n);
                bl[nt][1] = BS(s, 1, kwb + bq + 4, n);
            }
#pragma unroll
            for (int mt = 0; mt < 4; ++mt)
#pragma unroll
                for (int nt = 0; nt < 4; ++nt) {
                    mma_bf16(acc[mt][nt], ah[mt], bh[nt]);
                    mma_bf16(acc[mt][nt], ah[mt], bl[nt]);
                    mma_bf16(acc[mt][nt], al[mt], bh[nt]);
                }
        }

        if (it + 1 < GITERS) {
            const int ns = s ^ 1;
            *(uint4*)&AS(ns, 0, am, akw)     = rah0;
            *(uint4*)&AS(ns, 0, am, akw + 4) = rah1;
            *(uint4*)&AS(ns, 1, am, akw)     = ral0;
            *(uint4*)&AS(ns, 1, am, akw + 4) = ral1;
            *(uint4*)&BS(ns, 0, bfw, bnf)     = rbh0;
            *(uint4*)&BS(ns, 0, bfw, bnf + 4) = rbh1;
            *(uint4*)&BS(ns, 1, bfw, bnf)     = rbl0;
            *(uint4*)&BS(ns, 1, bfw, bnf + 4) = rbl1;
            __syncthreads();
        }
    }

    const int mbase = by * 128 + wm * 64 + (lane >> 2);
    const int nbase = bx * 128 + wn * 32 + (lane & 3) * 2;
#pragma unroll
    for (int mt = 0; mt < 4; ++mt) {
#pragma unroll
        for (int nt = 0; nt < 4; ++nt) {
            const int m = mbase + mt * 16;
            const int n = nbase + nt * 8;
            float* p = g_theta + (size_t)m * N_SZ + n;
            p[0] = acc[mt][nt][0];
            p[1] = acc[mt][nt][1];
            p[(size_t)8 * N_SZ]     = acc[mt][nt][2];
            p[(size_t)8 * N_SZ + 1] = acc[mt][nt][3];
        }
    }
#undef AS
#undef BS
}

// ---------------------------------------------------------------------------
// Fused box + pair kernel. One block per b, 256 threads.
//   Phase 1 (threads 0..63): per-box z/Z/concept/box-volume (LINEAR domain);
//           threads 64..255 concurrently load Wrel into smem.
//   Phase 2 (all 256): unordered pairs; per dim:
//           u1+u2 folded into ONE log: ln((1+e1)(1+e2)) = ln(1+e1+e2+e1e2)
//           side product kept linear  ->  cond = P_int * (1/P_box[j])
//   5 MUFU per dim, zero per-pair exp2/log2.
// ---------------------------------------------------------------------------
__global__ __launch_bounds__(256)
void fused_kernel(const float* __restrict__ bp, const float* __restrict__ Wprob,
                  const float* __restrict__ bprob, const float* __restrict__ Wbox,
                  const float* __restrict__ Wrel, const float* __restrict__ bbox,
                  const float* __restrict__ brel, float* __restrict__ out)
{
    const int b = blockIdx.x;
    const int tid = threadIdx.x;

    __shared__ __align__(16) float sz[K_SZ * D_SZ];   // 512
    __shared__ __align__(16) float sZ[K_SZ * D_SZ];   // 512
    __shared__ __align__(16) float srcp[K_SZ];        // 1 / box volume
    __shared__ __align__(16) float sw[K_SZ * K_SZ];   // Wrel
    __shared__ __align__(16) float sc[K_SZ * K_SZ];   // cond staging
    __shared__ float sbox[2];
    __shared__ float rr[8];

    // threads 64..255: load Wrel (overlaps box phase)
    if (tid >= 64) {
        for (int i = tid - 64; i < K_SZ * K_SZ; i += 192) sw[i] = Wrel[i];
    } else {
        // ---- box phase: one thread per k ----
        const int k = tid;
        const int lane = tid & 31;
        const float4* th4 = (const float4*)(g_theta + (size_t)b * N_SZ + k * 16);
        const float4* bp4 = (const float4*)(bp + k * 16);
        float4 t0 = th4[0], t1 = th4[1], t2 = th4[2], t3 = th4[3];
        float4 b0 = bp4[0], b1 = bp4[1], b2 = bp4[2], b3 = bp4[3];

        float z[8], Zb[8];
        float tz[8] = { t0.x + b0.x, t0.y + b0.y, t0.z + b0.z, t0.w + b0.w,
                        t1.x + b1.x, t1.y + b1.y, t1.z + b1.z, t1.w + b1.w };
        float tu[8] = { t2.x + b2.x, t2.y + b2.y, t2.z + b2.z, t2.w + b2.w,
                        t3.x + b3.x, t3.y + b3.y, t3.z + b3.z, t3.w + b3.w };
#pragma unroll
        for (int d = 0; d < 8; d++) {
            z[d]  = tz[d];
            Zb[d] = tz[d] + softplus_f(tu[d]);
        }

        // concept prob
        const float4* wp4 = (const float4*)(Wprob + k * 16);
        float4 w0 = wp4[0], w1 = wp4[1], w2 = wp4[2], w3 = wp4[3];
        const float wz[8] = { w0.x, w0.y, w0.z, w0.w, w1.x, w1.y, w1.z, w1.w };
        const float wZ[8] = { w2.x, w2.y, w2.z, w2.w, w3.x, w3.y, w3.z, w3.w };
        float logit = bprob[k];
#pragma unroll
        for (int d = 0; d < 8; d++)
            logit += z[d] * wz[d] + Zb[d] * wZ[d];
        float p = sigmoid_f(logit);
        out[OUT_CONCEPT_OFF + b * K_SZ + k] = p;

        // box volume (linear domain, clamped per side)
        float P = 1.0f;
#pragma unroll
        for (int d = 0; d < 8; d++) {
            float x = 2.0f * (Zb[d] - z[d]);           // >= 0
            float sp = x + __logf(1.0f + __expf(-x));
            P *= fmaxf(0.5f * sp, 1e-23f);
        }
        srcp[k] = 1.0f / P;

        // stash z/Z
#pragma unroll
        for (int d = 0; d < 8; d++) { sz[k * 8 + d] = z[d]; sZ[k * 8 + d] = Zb[d]; }

        // box part of final logit
        const float4* wb4 = (const float4*)(Wbox + k * 16);
        float4 v0 = wb4[0], v1 = wb4[1], v2 = wb4[2], v3 = wb4[3];
        const float wbz[8] = { v0.x, v0.y, v0.z, v0.w, v1.x, v1.y, v1.z, v1.w };
        const float wbZ[8] = { v2.x, v2.y, v2.z, v2.w, v3.x, v3.y, v3.z, v3.w };
        float c = 0.0f;
#pragma unroll
        for (int d = 0; d < 8; d++)
            c += z[d] * wbz[d] + Zb[d] * wbZ[d];
        c *= p;
#pragma unroll
        for (int off = 16; off > 0; off >>= 1)
            c += __shfl_down_sync(0xffffffffu, c, off);
        if (lane == 0) sbox[tid >> 5] = c;
    }
    __syncthreads();

    // ---- pair phase ----
    for (int p = tid; p < NPAIR; p += 256) {
        int i = (int)((sqrtf(8.0f * (float)p + 1.0f) - 1.0f) * 0.5f);
        while ((i + 1) * (i + 2) / 2 <= p) ++i;
        while (i * (i + 1) / 2 > p) --i;
        int j = p - i * (i + 1) / 2;

        const float* zi = sz + i * 8;
        const float* zj = sz + j * 8;
        const float* Zi = sZ + i * 8;
        const float* Zj = sZ + j * 8;

        float P = 1.0f;
#pragma unroll
        for (int d = 0; d < 8; d++) {
            float a = zi[d],  c = zj[d];
            float A = Zi[d],  C = Zj[d];
            float e1 = __expf(-10.0f * fabsf(a - c));
            float e2 = __expf(-10.0f * fabsf(A - C));
            // ln((1+e1)(1+e2)) in ONE log
            float w = __logf(1.0f + (e1 + e2 + e1 * e2));
            float gap = fminf(A, C) - fmaxf(a, c);
            float x = 2.0f * gap - 0.2f * w;
            float sp = fmaxf(x, 0.0f) + __logf(1.0f + __expf(-fabsf(x)));
            P *= fmaxf(0.5f * sp, 1e-23f);
        }

        float cij = P * srcp[j];
        cij = fminf(fmaxf(cij, 1e-6f), 1.0f - 1e-6f);
        float cji = P * srcp[i];
        cji = fminf(fmaxf(cji, 1e-6f), 1.0f - 1e-6f);
        sc[i * K_SZ + j] = cij;
        sc[j * K_SZ + i] = cji;
    }
    __syncthreads();

    // coalesced cond writeout + flat_rel @ Wrel
    float acc = 0.0f;
    float4* condout = (float4*)(out + OUT_COND_OFF + (size_t)b * (K_SZ * K_SZ));
    for (int q = tid; q < (K_SZ * K_SZ) / 4; q += 256) {
        float4 v = *(const float4*)&sc[q * 4];
        float4 w = *(const float4*)&sw[q * 4];
        condout[q] = v;
        acc += v.x * w.x + v.y * w.y + v.z * w.z + v.w * w.w;
    }

#pragma unroll
    for (int off = 16; off > 0; off >>= 1)
        acc += __shfl_down_sync(0xffffffffu, acc, off);
    if ((tid & 31) == 0) rr[tid >> 5] = acc;
    __syncthreads();
    if (tid == 0) {
        float s = 0.0f;
#pragma unroll
        for (int w = 0; w < 8; w++) s += rr[w];
        float logit = sbox[0] + sbox[1] + bbox[0] + s + brel[0];
        out[b] = sigmoid_f(logit);
    }
}

// ---------------------------------------------------------------------------
extern "C" void kernel_launch(void* const* d_in, const int* in_sizes, int n_in,
                              void* d_out, int out_size)
{
    const float* features = (const float*)d_in[0];
    const float* Wp       = (const float*)d_in[1];
    const float* bp       = (const float*)d_in[2];
    const float* Wprob    = (const float*)d_in[3];
    const float* bprob    = (const float*)d_in[4];
    const float* Wbox     = (const float*)d_in[5];
    const float* bbox     = (const float*)d_in[6];
    const float* Wrel     = (const float*)d_in[7];
    const float* brel     = (const float*)d_in[8];
    float* out = (float*)d_out;

    cudaFuncSetAttribute(gemm_bf16, cudaFuncAttributeMaxDynamicSharedMemorySize, SMEM_BYTES);

    convert_A<<<(B_SZ * F_SZ / 4) / 256, 256>>>(features);
    convert_B<<<(F_SZ / 2) * N_SZ / 256, 256>>>(Wp);
    gemm_bf16<<<dim3(8, 32), 256, SMEM_BYTES>>>();
    fused_kernel<<<B_SZ, 256>>>(bp, Wprob, bprob, Wbox, Wrel, bbox, brel, out);
}

// round 9
// speedup vs baseline: 2.0112x; 1.0524x over previous
#include <cuda_runtime.h>
#include <cuda_bf16.h>
#include <math.h>
#include <stdint.h>

// ---------------------------------------------------------------------------
// Problem constants
// ---------------------------------------------------------------------------
#define B_SZ 4096
#define K_SZ 64
#define D_SZ 8
#define F_SZ 2048
#define N_SZ 1024
#define NPAIR (K_SZ * (K_SZ + 1) / 2)

#define OUT_CONCEPT_OFF (B_SZ)
#define OUT_COND_OFF (B_SZ + B_SZ * K_SZ)

// GEMM tiling: block 128x128, BK=32 (16 bf16x2 words), 2-stage smem pipeline
#define GITERS (F_SZ / 32)        // 64
#define ASTRIDE 20
#define BSTRIDE 136
#define A_PLANE_W (128 * ASTRIDE)
#define B_PLANE_W (16 * BSTRIDE)
#define STAGE_W (2 * A_PLANE_W + 2 * B_PLANE_W)
#define SMEM_BYTES (2 * STAGE_W * 4)

// ---------------------------------------------------------------------------
// Scratch (__device__ globals; no allocation)
// ---------------------------------------------------------------------------
__device__ __align__(256) float g_theta[(size_t)B_SZ * N_SZ];

// pre-split bf16 operands, packed as bf16x2 words
__device__ uint32_t g_AhiW[(size_t)B_SZ * (F_SZ / 2)];
__device__ uint32_t g_AloW[(size_t)B_SZ * (F_SZ / 2)];
__device__ uint32_t g_BhiW[(size_t)(F_SZ / 2) * N_SZ];
__device__ uint32_t g_BloW[(size_t)(F_SZ / 2) * N_SZ];

// ---------------------------------------------------------------------------
// math helpers
// ---------------------------------------------------------------------------
__device__ __forceinline__ float ex2f(float x) {
    float r; asm("ex2.approx.ftz.f32 %0, %1;" : "=f"(r) : "f"(x)); return r;
}
__device__ __forceinline__ float lg2f(float x) {
    float r; asm("lg2.approx.ftz.f32 %0, %1;" : "=f"(r) : "f"(x)); return r;
}
#define C_L2E   1.4426950408889634f
#define C_LN2   0.6931471805599453f

__device__ __forceinline__ float softplus_f(float x) {
    // ln(1+e^x) = max(x,0) + LN2*lg2(1+ex2(-L2E*|x|))
    float u = ex2f(-C_L2E * fabsf(x));
    return fmaxf(x, 0.0f) + C_LN2 * lg2f(1.0f + u);
}
__device__ __forceinline__ float sigmoid_f(float x) {
    return 1.0f / (1.0f + ex2f(-C_L2E * x));
}

__device__ __forceinline__ void mma_bf16(float* c, const uint32_t* a, const uint32_t* b) {
    asm volatile(
        "mma.sync.aligned.m16n8k16.row.col.f32.bf16.bf16.f32 "
        "{%0,%1,%2,%3}, {%4,%5,%6,%7}, {%8,%9}, {%0,%1,%2,%3};"
        : "+f"(c[0]), "+f"(c[1]), "+f"(c[2]), "+f"(c[3])
        : "r"(a[0]), "r"(a[1]), "r"(a[2]), "r"(a[3]), "r"(b[0]), "r"(b[1]));
}

__device__ __forceinline__ uint32_t pack_hi(float x, float y) {
    __nv_bfloat162 v = __halves2bfloat162(__float2bfloat16(x), __float2bfloat16(y));
    return *(uint32_t*)&v;
}
__device__ __forceinline__ uint32_t pack_lo(float x, float y) {
    __nv_bfloat16 hx = __float2bfloat16(x);
    __nv_bfloat16 hy = __float2bfloat16(y);
    __nv_bfloat162 v = __halves2bfloat162(__float2bfloat16(x - __bfloat162float(hx)),
                                          __float2bfloat16(y - __bfloat162float(hy)));
    return *(uint32_t*)&v;
}

// ---------------------------------------------------------------------------
// Convert A: fp32 [4096,2048] -> packed bf16x2 hi/lo word arrays
// ---------------------------------------------------------------------------
__global__ __launch_bounds__(256)
void convert_A(const float* __restrict__ A)
{
    int gid = blockIdx.x * 256 + threadIdx.x;
    float4 v = *(const float4*)(A + (size_t)gid * 4);
    uint2 hi = make_uint2(pack_hi(v.x, v.y), pack_hi(v.z, v.w));
    uint2 lo = make_uint2(pack_lo(v.x, v.y), pack_lo(v.z, v.w));
    *(uint2*)(g_AhiW + (size_t)gid * 2) = hi;
    *(uint2*)(g_AloW + (size_t)gid * 2) = lo;
}

// ---------------------------------------------------------------------------
// Convert B: Wp[k][f][d] (n = k*16+d) -> word(fw, n) arrays
// ---------------------------------------------------------------------------
__global__ __launch_bounds__(256)
void convert_B(const float* __restrict__ Wp)
{
    int gid = blockIdx.x * 256 + threadIdx.x;
    int fw = gid >> 10;
    int n  = gid & 1023;
    int k = n >> 4, d = n & 15;
    const float* base = Wp + (size_t)k * (F_SZ * 16) + d;
    float x = base[(size_t)(2 * fw) * 16];
    float y = base[(size_t)(2 * fw + 1) * 16];
    g_BhiW[gid] = pack_hi(x, y);
    g_BloW[gid] = pack_lo(x, y);
}

// ---------------------------------------------------------------------------
// bf16 3-pass tensor-core GEMM (unchanged — at the legacy HMMA HW floor)
// ---------------------------------------------------------------------------
__global__ __launch_bounds__(256, 1)
void gemm_bf16()
{
    extern __shared__ uint32_t sm[];
#define AS(s,p,m,kw) sm[(s) * STAGE_W + (p) * A_PLANE_W + (m) * ASTRIDE + (kw)]
#define BS(s,p,kw,n) sm[(s) * STAGE_W + 2 * A_PLANE_W + (p) * B_PLANE_W + (kw) * BSTRIDE + (n)]

    const int tid  = threadIdx.x;
    const int lane = tid & 31;
    const int warp = tid >> 5;
    const int wm = warp & 1;
    const int wn = warp >> 1;
    const int bx = blockIdx.x;
    const int by = blockIdx.y;

    const int am  = tid >> 1;
    const int akw = (tid & 1) * 8;
    const uint32_t* ApH = g_AhiW + (size_t)(by * 128 + am) * (F_SZ / 2) + akw;
    const uint32_t* ApL = g_AloW + (size_t)(by * 128 + am) * (F_SZ / 2) + akw;
    const int bfw = tid >> 4;
    const int bnf = (tid & 15) * 8;
    const uint32_t* BpH = g_BhiW + (size_t)bfw * N_SZ + bx * 128 + bnf;
    const uint32_t* BpL = g_BloW + (size_t)bfw * N_SZ + bx * 128 + bnf;

    float acc[4][4][4];
#pragma unroll
    for (int i = 0; i < 4; i++)
#pragma unroll
        for (int j = 0; j < 4; j++)
#pragma unroll
            for (int r = 0; r < 4; r++) acc[i][j][r] = 0.0f;

    uint4 rah0, rah1, ral0, ral1, rbh0, rbh1, rbl0, rbl1;

    rah0 = *(const uint4*)(ApH);      rah1 = *(const uint4*)(ApH + 4);
    ral0 = *(const uint4*)(ApL);      ral1 = *(const uint4*)(ApL + 4);
    rbh0 = *(const uint4*)(BpH);      rbh1 = *(const uint4*)(BpH + 4);
    rbl0 = *(const uint4*)(BpL);      rbl1 = *(const uint4*)(BpL + 4);
    *(uint4*)&AS(0, 0, am, akw)     = rah0;
    *(uint4*)&AS(0, 0, am, akw + 4) = rah1;
    *(uint4*)&AS(0, 1, am, akw)     = ral0;
    *(uint4*)&AS(0, 1, am, akw + 4) = ral1;
    *(uint4*)&BS(0, 0, bfw, bnf)     = rbh0;
    *(uint4*)&BS(0, 0, bfw, bnf + 4) = rbh1;
    *(uint4*)&BS(0, 1, bfw, bnf)     = rbl0;
    *(uint4*)&BS(0, 1, bfw, bnf + 4) = rbl1;
    __syncthreads();

    const int ar = lane >> 2;
    const int aq = lane & 3;
    const int bq = lane & 3;
    const int bc = lane >> 2;

    for (int it = 0; it < GITERS; ++it) {
        const int s = it & 1;

        if (it + 1 < GITERS) {
            const int kb = (it + 1) * 16;
            rah0 = *(const uint4*)(ApH + kb);
            rah1 = *(const uint4*)(ApH + kb + 4);
            ral0 = *(const uint4*)(ApL + kb);
            ral1 = *(const uint4*)(ApL + kb + 4);
            rbh0 = *(const uint4*)(BpH + (size_t)kb * N_SZ);
            rbh1 = *(const uint4*)(BpH + (size_t)kb * N_SZ + 4);
            rbl0 = *(const uint4*)(BpL + (size_t)kb * N_SZ);
            rbl1 = *(const uint4*)(BpL + (size_t)kb * N_SZ + 4);
        }

#pragma unroll
        for (int ks = 0; ks < 2; ++ks) {
            uint32_t ah[4][4], al[4][4], bh[4][2], bl[4][2];
            const int kwb = ks * 8;
#pragma unroll
            for (int mt = 0; mt < 4; ++mt) {
                const int row = wm * 64 + mt * 16 + ar;
                ah[mt][0] = AS(s, 0, row,     kwb + aq);
                ah[mt][1] = AS(s, 0, row + 8, kwb + aq);
                ah[mt][2] = AS(s, 0, row,     kwb + aq + 4);
                ah[mt][3] = AS(s, 0, row + 8, kwb + aq + 4);
                al[mt][0] = AS(s, 1, row,     kwb + aq);
                al[mt][1] = AS(s, 1, row + 8, kwb + aq);
                al[mt][2] = AS(s, 1, row,     kwb + aq + 4);
                al[mt][3] = AS(s, 1, row + 8, kwb + aq + 4);
            }
#pragma unroll
            for (int nt = 0; nt < 4; ++nt) {
                const int n = wn * 32 + nt * 8 + bc;
                bh[nt][0] = BS(s, 0, kwb + bq,     n);
                bh[nt][1] = BS(s, 0, kwb + bq + 4, n);
                bl[nt][0] = BS(s, 1, kwb + bq,     n);
                bl[nt][1] = BS(s, 1, kwb + bq + 4, n);
            }
#pragma unroll
            for (int mt = 0; mt < 4; ++mt)
#pragma unroll
                for (int nt = 0; nt < 4; ++nt) {
                    mma_bf16(acc[mt][nt], ah[mt], bh[nt]);
                    mma_bf16(acc[mt][nt], ah[mt], bl[nt]);
                    mma_bf16(acc[mt][nt], al[mt], bh[nt]);
                }
        }

        if (it + 1 < GITERS) {
            const int ns = s ^ 1;
            *(uint4*)&AS(ns, 0, am, akw)     = rah0;
            *(uint4*)&AS(ns, 0, am, akw + 4) = rah1;
            *(uint4*)&AS(ns, 1, am, akw)     = ral0;
            *(uint4*)&AS(ns, 1, am, akw + 4) = ral1;
            *(uint4*)&BS(ns, 0, bfw, bnf)     = rbh0;
            *(uint4*)&BS(ns, 0, bfw, bnf + 4) = rbh1;
            *(uint4*)&BS(ns, 1, bfw, bnf)     = rbl0;
            *(uint4*)&BS(ns, 1, bfw, bnf + 4) = rbl1;
            __syncthreads();
        }
    }

    const int mbase = by * 128 + wm * 64 + (lane >> 2);
    const int nbase = bx * 128 + wn * 32 + (lane & 3) * 2;
#pragma unroll
    for (int mt = 0; mt < 4; ++mt) {
#pragma unroll
        for (int nt = 0; nt < 4; ++nt) {
            const int m = mbase + mt * 16;
            const int n = nbase + nt * 8;
            float* p = g_theta + (size_t)m * N_SZ + n;
            p[0] = acc[mt][nt][0];
            p[1] = acc[mt][nt][1];
            p[(size_t)8 * N_SZ]     = acc[mt][nt][2];
            p[(size_t)8 * N_SZ + 1] = acc[mt][nt][3];
        }
    }
#undef AS
#undef BS
}

// ---------------------------------------------------------------------------
// Fused box + pair kernel, instruction-dieted.
//  - pair (i,j) via smem uint16 table (built with integer ops, no sqrt)
//  - z/Z loaded as float4 (8 LDS.128/pair instead of 32 LDS.32)
//  - raw ex2/lg2 with pre-folded constants
//  - unscaled sides: the 0.5^8 factors cancel in cond = P_int/P_box
// ---------------------------------------------------------------------------
__global__ __launch_bounds__(256)
void fused_kernel(const float* __restrict__ bp, const float* __restrict__ Wprob,
                  const float* __restrict__ bprob, const float* __restrict__ Wbox,
                  const float* __restrict__ Wrel, const float* __restrict__ bbox,
                  const float* __restrict__ brel, float* __restrict__ out)
{
    const int b = blockIdx.x;
    const int tid = threadIdx.x;

    __shared__ __align__(16) float sz[K_SZ * D_SZ];
    __shared__ __align__(16) float sZ[K_SZ * D_SZ];
    __shared__ __align__(16) float srcp[K_SZ];
    __shared__ __align__(16) float sw[K_SZ * K_SZ];
    __shared__ __align__(16) float sc[K_SZ * K_SZ];
    __shared__ __align__(16) uint16_t stbl[NPAIR];
    __shared__ float sbox[2];
    __shared__ float rr[8];

    if (tid >= 64) {
        // load Wrel (overlaps box phase)
        for (int i = tid - 64; i < K_SZ * K_SZ; i += 192) sw[i] = Wrel[i];
    } else {
        // ---- box phase: one thread per k ----
        const int k = tid;
        const int lane = tid & 31;
        const float4* th4 = (const float4*)(g_theta + (size_t)b * N_SZ + k * 16);
        const float4* bp4 = (const float4*)(bp + k * 16);
        float4 t0 = th4[0], t1 = th4[1], t2 = th4[2], t3 = th4[3];
        float4 b0 = bp4[0], b1 = bp4[1], b2 = bp4[2], b3 = bp4[3];

        float z[8], Zb[8];
        float tz[8] = { t0.x + b0.x, t0.y + b0.y, t0.z + b0.z, t0.w + b0.w,
                        t1.x + b1.x, t1.y + b1.y, t1.z + b1.z, t1.w + b1.w };
        float tu[8] = { t2.x + b2.x, t2.y + b2.y, t2.z + b2.z, t2.w + b2.w,
                        t3.x + b3.x, t3.y + b3.y, t3.z + b3.z, t3.w + b3.w };
#pragma unroll
        for (int d = 0; d < 8; d++) {
            z[d]  = tz[d];
            Zb[d] = tz[d] + softplus_f(tu[d]);
        }

        // concept prob
        const float4* wp4 = (const float4*)(Wprob + k * 16);
        float4 w0 = wp4[0], w1 = wp4[1], w2 = wp4[2], w3 = wp4[3];
        const float wz[8] = { w0.x, w0.y, w0.z, w0.w, w1.x, w1.y, w1.z, w1.w };
        const float wZ[8] = { w2.x, w2.y, w2.z, w2.w, w3.x, w3.y, w3.z, w3.w };
        float logit = bprob[k];
#pragma unroll
        for (int d = 0; d < 8; d++)
            logit += z[d] * wz[d] + Zb[d] * wZ[d];
        float p = sigmoid_f(logit);
        out[OUT_CONCEPT_OFF + b * K_SZ + k] = p;

        // box volume, UNSCALED sides: side = softplus(2*(Z-z)), clamp 2e-23
        float P = 1.0f;
#pragma unroll
        for (int d = 0; d < 8; d++) {
            float x = 2.0f * (Zb[d] - z[d]);               // >= 0
            float u = ex2f(-C_L2E * x);
            float sp = x + C_LN2 * lg2f(1.0f + u);
            P *= fmaxf(sp, 2e-23f);
        }
        srcp[k] = 1.0f / P;

#pragma unroll
        for (int d = 0; d < 8; d++) { sz[k * 8 + d] = z[d]; sZ[k * 8 + d] = Zb[d]; }

        // box part of final logit
        const float4* wb4 = (const float4*)(Wbox + k * 16);
        float4 v0 = wb4[0], v1 = wb4[1], v2 = wb4[2], v3 = wb4[3];
        const float wbz[8] = { v0.x, v0.y, v0.z, v0.w, v1.x, v1.y, v1.z, v1.w };
        const float wbZ[8] = { v2.x, v2.y, v2.z, v2.w, v3.x, v3.y, v3.z, v3.w };
        float c = 0.0f;
#pragma unroll
        for (int d = 0; d < 8; d++)
            c += z[d] * wbz[d] + Zb[d] * wbZ[d];
        c *= p;
#pragma unroll
        for (int off = 16; off > 0; off >>= 1)
            c += __shfl_down_sync(0xffffffffu, c, off);
        if (lane == 0) sbox[tid >> 5] = c;

        // build pair-index table for row k (pure integer)
        int base = k * (k + 1) / 2;
        for (int j = 0; j <= k; j++)
            stbl[base + j] = (uint16_t)((k << 6) | j);
    }
    __syncthreads();

    // ---- pair phase ----
    for (int p = tid; p < NPAIR; p += 256) {
        const int v = stbl[p];
        const int i = v >> 6, j = v & 63;

        float za[8], zc[8], ZA[8], ZC[8];
        *(float4*)&za[0] = *(const float4*)&sz[i * 8];
        *(float4*)&za[4] = *(const float4*)&sz[i * 8 + 4];
        *(float4*)&zc[0] = *(const float4*)&sz[j * 8];
        *(float4*)&zc[4] = *(const float4*)&sz[j * 8 + 4];
        *(float4*)&ZA[0] = *(const float4*)&sZ[i * 8];
        *(float4*)&ZA[4] = *(const float4*)&sZ[i * 8 + 4];
        *(float4*)&ZC[0] = *(const float4*)&sZ[j * 8];
        *(float4*)&ZC[4] = *(const float4*)&sZ[j * 8 + 4];

        float P = 1.0f;
#pragma unroll
        for (int d = 0; d < 8; d++) {
            float d1 = za[d] - zc[d];
            float d2 = ZA[d] - ZC[d];
            float e1 = ex2f(-10.0f * C_L2E * fabsf(d1));
            float e2 = ex2f(-10.0f * C_L2E * fabsf(d2));
            float s  = fmaf(e1, e2, e1) + e2;
            float t2 = lg2f(1.0f + s);
            float gap = fminf(ZA[d], ZC[d]) - fmaxf(za[d], zc[d]);
            float x  = fmaf(-0.2f * C_LN2, t2, gap + gap);
            float u  = ex2f(-C_L2E * fabsf(x));
            float vv = lg2f(1.0f + u);
            float sp = fmaf(C_LN2, vv, fmaxf(x, 0.0f));
            P *= fmaxf(sp, 2e-23f);
        }

        float cij = P * srcp[j];
        cij = fminf(fmaxf(cij, 1e-6f), 1.0f - 1e-6f);
        float cji = P * srcp[i];
        cji = fminf(fmaxf(cji, 1e-6f), 1.0f - 1e-6f);
        sc[i * K_SZ + j] = cij;
        sc[j * K_SZ + i] = cji;
    }
    __syncthreads();

    // coalesced cond writeout + flat_rel @ Wrel
    float acc = 0.0f;
    float4* condout = (float4*)(out + OUT_COND_OFF + (size_t)b * (K_SZ * K_SZ));
    for (int q = tid; q < (K_SZ * K_SZ) / 4; q += 256) {
        float4 v = *(const float4*)&sc[q * 4];
        float4 w = *(const float4*)&sw[q * 4];
        condout[q] = v;
        acc += v.x * w.x + v.y * w.y + v.z * w.z + v.w * w.w;
    }

#pragma unroll
    for (int off = 16; off > 0; off >>= 1)
        acc += __shfl_down_sync(0xffffffffu, acc, off);
    if ((tid & 31) == 0) rr[tid >> 5] = acc;
    __syncthreads();
    if (tid == 0) {
        float s = 0.0f;
#pragma unroll
        for (int w = 0; w < 8; w++) s += rr[w];
        float logit = sbox[0] + sbox[1] + bbox[0] + s + brel[0];
        out[b] = sigmoid_f(logit);
    }
}

// ---------------------------------------------------------------------------
extern "C" void kernel_launch(void* const* d_in, const int* in_sizes, int n_in,
                              void* d_out, int out_size)
{
    const float* features = (const float*)d_in[0];
    const float* Wp       = (const float*)d_in[1];
    const float* bp       = (const float*)d_in[2];
    const float* Wprob    = (const float*)d_in[3];
    const float* bprob    = (const float*)d_in[4];
    const float* Wbox     = (const float*)d_in[5];
    const float* bbox     = (const float*)d_in[6];
    const float* Wrel     = (const float*)d_in[7];
    const float* brel     = (const float*)d_in[8];
    float* out = (float*)d_out;

    cudaFuncSetAttribute(gemm_bf16, cudaFuncAttributeMaxDynamicSharedMemorySize, SMEM_BYTES);

    convert_A<<<(B_SZ * F_SZ / 4) / 256, 256>>>(features);
    convert_B<<<(F_SZ / 2) * N_SZ / 256, 256>>>(Wp);
    gemm_bf16<<<dim3(8, 32), 256, SMEM_BYTES>>>();
    fused_kernel<<<B_SZ, 256>>>(bp, Wprob, bprob, Wbox, Wrel, bbox, brel, out);
}

// round 10
// speedup vs baseline: 2.0836x; 1.0360x over previous
#include <cuda_runtime.h>
#include <cuda_bf16.h>
#include <math.h>
#include <stdint.h>

// ---------------------------------------------------------------------------
// Problem constants
// ---------------------------------------------------------------------------
#define B_SZ 4096
#define K_SZ 64
#define D_SZ 8
#define F_SZ 2048
#define N_SZ 1024
#define NPAIR (K_SZ * (K_SZ + 1) / 2)
#define NTILE 272                 // 4x2 pair tiles covering lower triangle

#define OUT_CONCEPT_OFF (B_SZ)
#define OUT_COND_OFF (B_SZ + B_SZ * K_SZ)

// GEMM tiling: block 128x128, BK=32 (16 bf16x2 words), 2-stage smem pipeline
#define GITERS (F_SZ / 32)        // 64
#define ASTRIDE 20
#define BSTRIDE 136
#define A_PLANE_W (128 * ASTRIDE)
#define B_PLANE_W (16 * BSTRIDE)
#define STAGE_W (2 * A_PLANE_W + 2 * B_PLANE_W)
#define SMEM_BYTES (2 * STAGE_W * 4)

// ---------------------------------------------------------------------------
// Scratch (__device__ globals; no allocation)
// ---------------------------------------------------------------------------
__device__ __align__(256) float g_theta[(size_t)B_SZ * N_SZ];

// pre-split bf16 operands, packed as bf16x2 words
__device__ uint32_t g_AhiW[(size_t)B_SZ * (F_SZ / 2)];
__device__ uint32_t g_AloW[(size_t)B_SZ * (F_SZ / 2)];
__device__ uint32_t g_BhiW[(size_t)(F_SZ / 2) * N_SZ];
__device__ uint32_t g_BloW[(size_t)(F_SZ / 2) * N_SZ];

// ---------------------------------------------------------------------------
// math helpers
// ---------------------------------------------------------------------------
__device__ __forceinline__ float ex2f(float x) {
    float r; asm("ex2.approx.ftz.f32 %0, %1;" : "=f"(r) : "f"(x)); return r;
}
__device__ __forceinline__ float lg2f(float x) {
    float r; asm("lg2.approx.ftz.f32 %0, %1;" : "=f"(r) : "f"(x)); return r;
}
#define C_L2E   1.4426950408889634f
#define C_LN2   0.6931471805599453f

__device__ __forceinline__ float softplus_f(float x) {
    float u = ex2f(-C_L2E * fabsf(x));
    return fmaxf(x, 0.0f) + C_LN2 * lg2f(1.0f + u);
}
__device__ __forceinline__ float sigmoid_f(float x) {
    return 1.0f / (1.0f + ex2f(-C_L2E * x));
}

__device__ __forceinline__ void mma_bf16(float* c, const uint32_t* a, const uint32_t* b) {
    asm volatile(
        "mma.sync.aligned.m16n8k16.row.col.f32.bf16.bf16.f32 "
        "{%0,%1,%2,%3}, {%4,%5,%6,%7}, {%8,%9}, {%0,%1,%2,%3};"
        : "+f"(c[0]), "+f"(c[1]), "+f"(c[2]), "+f"(c[3])
        : "r"(a[0]), "r"(a[1]), "r"(a[2]), "r"(a[3]), "r"(b[0]), "r"(b[1]));
}

__device__ __forceinline__ uint32_t pack_hi(float x, float y) {
    __nv_bfloat162 v = __halves2bfloat162(__float2bfloat16(x), __float2bfloat16(y));
    return *(uint32_t*)&v;
}
__device__ __forceinline__ uint32_t pack_lo(float x, float y) {
    __nv_bfloat16 hx = __float2bfloat16(x);
    __nv_bfloat16 hy = __float2bfloat16(y);
    __nv_bfloat162 v = __halves2bfloat162(__float2bfloat16(x - __bfloat162float(hx)),
                                          __float2bfloat16(y - __bfloat162float(hy)));
    return *(uint32_t*)&v;
}

// ---------------------------------------------------------------------------
// Convert A: fp32 [4096,2048] -> packed bf16x2 hi/lo word arrays
// ---------------------------------------------------------------------------
__global__ __launch_bounds__(256)
void convert_A(const float* __restrict__ A)
{
    int gid = blockIdx.x * 256 + threadIdx.x;
    float4 v = *(const float4*)(A + (size_t)gid * 4);
    uint2 hi = make_uint2(pack_hi(v.x, v.y), pack_hi(v.z, v.w));
    uint2 lo = make_uint2(pack_lo(v.x, v.y), pack_lo(v.z, v.w));
    *(uint2*)(g_AhiW + (size_t)gid * 2) = hi;
    *(uint2*)(g_AloW + (size_t)gid * 2) = lo;
}

// ---------------------------------------------------------------------------
// Convert B: Wp[k][f][d] (n = k*16+d) -> word(fw, n) arrays
// ---------------------------------------------------------------------------
__global__ __launch_bounds__(256)
void convert_B(const float* __restrict__ Wp)
{
    int gid = blockIdx.x * 256 + threadIdx.x;
    int fw = gid >> 10;
    int n  = gid & 1023;
    int k = n >> 4, d = n & 15;
    const float* base = Wp + (size_t)k * (F_SZ * 16) + d;
    float x = base[(size_t)(2 * fw) * 16];
    float y = base[(size_t)(2 * fw + 1) * 16];
    g_BhiW[gid] = pack_hi(x, y);
    g_BloW[gid] = pack_lo(x, y);
}

// ---------------------------------------------------------------------------
// bf16 3-pass tensor-core GEMM (unchanged — at the legacy HMMA HW floor)
// ---------------------------------------------------------------------------
__global__ __launch_bounds__(256, 1)
void gemm_bf16()
{
    extern __shared__ uint32_t sm[];
#define AS(s,p,m,kw) sm[(s) * STAGE_W + (p) * A_PLANE_W + (m) * ASTRIDE + (kw)]
#define BS(s,p,kw,n) sm[(s) * STAGE_W + 2 * A_PLANE_W + (p) * B_PLANE_W + (kw) * BSTRIDE + (n)]

    const int tid  = threadIdx.x;
    const int lane = tid & 31;
    const int warp = tid >> 5;
    const int wm = warp & 1;
    const int wn = warp >> 1;
    const int bx = blockIdx.x;
    const int by = blockIdx.y;

    const int am  = tid >> 1;
    const int akw = (tid & 1) * 8;
    const uint32_t* ApH = g_AhiW + (size_t)(by * 128 + am) * (F_SZ / 2) + akw;
    const uint32_t* ApL = g_AloW + (size_t)(by * 128 + am) * (F_SZ / 2) + akw;
    const int bfw = tid >> 4;
    const int bnf = (tid & 15) * 8;
    const uint32_t* BpH = g_BhiW + (size_t)bfw * N_SZ + bx * 128 + bnf;
    const uint32_t* BpL = g_BloW + (size_t)bfw * N_SZ + bx * 128 + bnf;

    float acc[4][4][4];
#pragma unroll
    for (int i = 0; i < 4; i++)
#pragma unroll
        for (int j = 0; j < 4; j++)
#pragma unroll
            for (int r = 0; r < 4; r++) acc[i][j][r] = 0.0f;

    uint4 rah0, rah1, ral0, ral1, rbh0, rbh1, rbl0, rbl1;

    rah0 = *(const uint4*)(ApH);      rah1 = *(const uint4*)(ApH + 4);
    ral0 = *(const uint4*)(ApL);      ral1 = *(const uint4*)(ApL + 4);
    rbh0 = *(const uint4*)(BpH);      rbh1 = *(const uint4*)(BpH + 4);
    rbl0 = *(const uint4*)(BpL);      rbl1 = *(const uint4*)(BpL + 4);
    *(uint4*)&AS(0, 0, am, akw)     = rah0;
    *(uint4*)&AS(0, 0, am, akw + 4) = rah1;
    *(uint4*)&AS(0, 1, am, akw)     = ral0;
    *(uint4*)&AS(0, 1, am, akw + 4) = ral1;
    *(uint4*)&BS(0, 0, bfw, bnf)     = rbh0;
    *(uint4*)&BS(0, 0, bfw, bnf + 4) = rbh1;
    *(uint4*)&BS(0, 1, bfw, bnf)     = rbl0;
    *(uint4*)&BS(0, 1, bfw, bnf + 4) = rbl1;
    __syncthreads();

    const int ar = lane >> 2;
    const int aq = lane & 3;
    const int bq = lane & 3;
    const int bc = lane >> 2;

    for (int it = 0; it < GITERS; ++it) {
        const int s = it & 1;

        if (it + 1 < GITERS) {
            const int kb = (it + 1) * 16;
            rah0 = *(const uint4*)(ApH + kb);
            rah1 = *(const uint4*)(ApH + kb + 4);
            ral0 = *(const uint4*)(ApL + kb);
            ral1 = *(const uint4*)(ApL + kb + 4);
            rbh0 = *(const uint4*)(BpH + (size_t)kb * N_SZ);
            rbh1 = *(const uint4*)(BpH + (size_t)kb * N_SZ + 4);
            rbl0 = *(const uint4*)(BpL + (size_t)kb * N_SZ);
            rbl1 = *(const uint4*)(BpL + (size_t)kb * N_SZ + 4);
        }

#pragma unroll
        for (int ks = 0; ks < 2; ++ks) {
            uint32_t ah[4][4], al[4][4], bh[4][2], bl[4][2];
            const int kwb = ks * 8;
#pragma unroll
            for (int mt = 0; mt < 4; ++mt) {
                const int row = wm * 64 + mt * 16 + ar;
                ah[mt][0] = AS(s, 0, row,     kwb + aq);
                ah[mt][1] = AS(s, 0, row + 8, kwb + aq);
                ah[mt][2] = AS(s, 0, row,     kwb + aq + 4);
                ah[mt][3] = AS(s, 0, row + 8, kwb + aq + 4);
                al[mt][0] = AS(s, 1, row,     kwb + aq);
                al[mt][1] = AS(s, 1, row + 8, kwb + aq);
                al[mt][2] = AS(s, 1, row,     kwb + aq + 4);
                al[mt][3] = AS(s, 1, row + 8, kwb + aq + 4);
            }
#pragma unroll
            for (int nt = 0; nt < 4; ++nt) {
                const int n = wn * 32 + nt * 8 + bc;
                bh[nt][0] = BS(s, 0, kwb + bq,     n);
                bh[nt][1] = BS(s, 0, kwb + bq + 4, n);
                bl[nt][0] = BS(s, 1, kwb + bq,     n);
                bl[nt][1] = BS(s, 1, kwb + bq + 4, n);
            }
#pragma unroll
            for (int mt = 0; mt < 4; ++mt)
#pragma unroll
                for (int nt = 0; nt < 4; ++nt) {
                    mma_bf16(acc[mt][nt], ah[mt], bh[nt]);
                    mma_bf16(acc[mt][nt], ah[mt], bl[nt]);
                    mma_bf16(acc[mt][nt], al[mt], bh[nt]);
                }
        }

        if (it + 1 < GITERS) {
            const int ns = s ^ 1;
            *(uint4*)&AS(ns, 0, am, akw)     = rah0;
            *(uint4*)&AS(ns, 0, am, akw + 4) = rah1;
            *(uint4*)&AS(ns, 1, am, akw)     = ral0;
            *(uint4*)&AS(ns, 1, am, akw + 4) = ral1;
            *(uint4*)&BS(ns, 0, bfw, bnf)     = rbh0;
            *(uint4*)&BS(ns, 0, bfw, bnf + 4) = rbh1;
            *(uint4*)&BS(ns, 1, bfw, bnf)     = rbl0;
            *(uint4*)&BS(ns, 1, bfw, bnf + 4) = rbl1;
            __syncthreads();
        }
    }

    const int mbase = by * 128 + wm * 64 + (lane >> 2);
    const int nbase = bx * 128 + wn * 32 + (lane & 3) * 2;
#pragma unroll
    for (int mt = 0; mt < 4; ++mt) {
#pragma unroll
        for (int nt = 0; nt < 4; ++nt) {
            const int m = mbase + mt * 16;
            const int n = nbase + nt * 8;
            float* p = g_theta + (size_t)m * N_SZ + n;
            p[0] = acc[mt][nt][0];
            p[1] = acc[mt][nt][1];
            p[(size_t)8 * N_SZ]     = acc[mt][nt][2];
            p[(size_t)8 * N_SZ + 1] = acc[mt][nt][3];
        }
    }
#undef AS
#undef BS
}

// ---------------------------------------------------------------------------
// Fused box + pair kernel, 4x2 pair tiling + transposed box layout.
//  - szt[d][k] layout: lanes address by k -> <=2-way bank conflicts
//  - each thread computes an 8-pair tile; operand LDS amortized 8x
//  - per-pair math identical (order included) to R9
// ---------------------------------------------------------------------------
__global__ __launch_bounds__(256)
void fused_kernel(const float* __restrict__ bp, const float* __restrict__ Wprob,
                  const float* __restrict__ bprob, const float* __restrict__ Wbox,
                  const float* __restrict__ Wrel, const float* __restrict__ bbox,
                  const float* __restrict__ brel, float* __restrict__ out)
{
    const int b = blockIdx.x;
    const int tid = threadIdx.x;

    __shared__ __align__(16) float szt[D_SZ * K_SZ];   // [d][k]
    __shared__ __align__(16) float sZt[D_SZ * K_SZ];   // [d][k]
    __shared__ __align__(16) float srcp[K_SZ];
    __shared__ __align__(16) float sw[K_SZ * K_SZ];
    __shared__ __align__(16) float sc[K_SZ * K_SZ];
    __shared__ __align__(16) uint16_t stbl[NTILE];
    __shared__ float sbox[2];
    __shared__ float rr[8];

    if (tid >= 64) {
        for (int i = tid - 64; i < K_SZ * K_SZ; i += 192) sw[i] = Wrel[i];
    } else {
        // ---- box phase: one thread per k ----
        const int k = tid;
        const int lane = tid & 31;
        const float4* th4 = (const float4*)(g_theta + (size_t)b * N_SZ + k * 16);
        const float4* bp4 = (const float4*)(bp + k * 16);
        float4 t0 = th4[0], t1 = th4[1], t2 = th4[2], t3 = th4[3];
        float4 b0 = bp4[0], b1 = bp4[1], b2 = bp4[2], b3 = bp4[3];

        float z[8], Zb[8];
        float tz[8] = { t0.x + b0.x, t0.y + b0.y, t0.z + b0.z, t0.w + b0.w,
                        t1.x + b1.x, t1.y + b1.y, t1.z + b1.z, t1.w + b1.w };
        float tu[8] = { t2.x + b2.x, t2.y + b2.y, t2.z + b2.z, t2.w + b2.w,
                        t3.x + b3.x, t3.y + b3.y, t3.z + b3.z, t3.w + b3.w };
#pragma unroll
        for (int d = 0; d < 8; d++) {
            z[d]  = tz[d];
            Zb[d] = tz[d] + softplus_f(tu[d]);
        }

        // concept prob
        const float4* wp4 = (const float4*)(Wprob + k * 16);
        float4 w0 = wp4[0], w1 = wp4[1], w2 = wp4[2], w3 = wp4[3];
        const float wz[8] = { w0.x, w0.y, w0.z, w0.w, w1.x, w1.y, w1.z, w1.w };
        const float wZ[8] = { w2.x, w2.y, w2.z, w2.w, w3.x, w3.y, w3.z, w3.w };
        float logit = bprob[k];
#pragma unroll
        for (int d = 0; d < 8; d++)
            logit += z[d] * wz[d] + Zb[d] * wZ[d];
        float p = sigmoid_f(logit);
        out[OUT_CONCEPT_OFF + b * K_SZ + k] = p;

        // box volume, unscaled sides
        float P = 1.0f;
#pragma unroll
        for (int d = 0; d < 8; d++) {
            float x = 2.0f * (Zb[d] - z[d]);
            float u = ex2f(-C_L2E * x);
            float sp = x + C_LN2 * lg2f(1.0f + u);
            P *= fmaxf(sp, 2e-23f);
        }
        srcp[k] = 1.0f / P;

        // transposed stash
#pragma unroll
        for (int d = 0; d < 8; d++) { szt[d * K_SZ + k] = z[d]; sZt[d * K_SZ + k] = Zb[d]; }

        // box part of final logit
        const float4* wb4 = (const float4*)(Wbox + k * 16);
        float4 v0 = wb4[0], v1 = wb4[1], v2 = wb4[2], v3 = wb4[3];
        const float wbz[8] = { v0.x, v0.y, v0.z, v0.w, v1.x, v1.y, v1.z, v1.w };
        const float wbZ[8] = { v2.x, v2.y, v2.z, v2.w, v3.x, v3.y, v3.z, v3.w };
        float c = 0.0f;
#pragma unroll
        for (int d = 0; d < 8; d++)
            c += z[d] * wbz[d] + Zb[d] * wbZ[d];
        c *= p;
#pragma unroll
        for (int off = 16; off > 0; off >>= 1)
            c += __shfl_down_sync(0xffffffffu, c, off);
        if (lane == 0) sbox[tid >> 5] = c;

        // tile table: ti in 0..15 (4 rows each), tj in 0..2*ti+1 (2 cols each)
        if (k < 16) {
            const int ti = k;
            const int base = ti * ti + ti;   // sum of (2t+2)
            for (int tj = 0; tj <= 2 * ti + 1; tj++)
                stbl[base + tj] = (uint16_t)((ti << 6) | tj);
        }
    }
    __syncthreads();

    // ---- pair phase: one 4x2 tile (8 pairs) per unit ----
    for (int u = tid; u < NTILE; u += 256) {
        const int v = stbl[u];
        const int i0 = (v >> 6) * 4;
        const int j0 = (v & 63) * 2;

        float P[8];
#pragma unroll
        for (int q = 0; q < 8; q++) P[q] = 1.0f;

#pragma unroll 1
        for (int d = 0; d < 8; d++) {
            const float* zr = szt + d * K_SZ;
            const float* Zr = sZt + d * K_SZ;
            float zi[4], Zi[4], zj[2], Zj[2];
#pragma unroll
            for (int ii = 0; ii < 4; ii++) { zi[ii] = zr[i0 + ii]; Zi[ii] = Zr[i0 + ii]; }
#pragma unroll
            for (int jj = 0; jj < 2; jj++) { zj[jj] = zr[j0 + jj]; Zj[jj] = Zr[j0 + jj]; }

#pragma unroll
            for (int ii = 0; ii < 4; ii++) {
#pragma unroll
                for (int jj = 0; jj < 2; jj++) {
                    float d1 = zi[ii] - zj[jj];
                    float d2 = Zi[ii] - Zj[jj];
                    float e1 = ex2f(-10.0f * C_L2E * fabsf(d1));
                    float e2 = ex2f(-10.0f * C_L2E * fabsf(d2));
                    float s  = fmaf(e1, e2, e1) + e2;
                    float t2 = lg2f(1.0f + s);
                    float gap = fminf(Zi[ii], Zj[jj]) - fmaxf(zi[ii], zj[jj]);
                    float x  = fmaf(-0.2f * C_LN2, t2, gap + gap);
                    float uu = ex2f(-C_L2E * fabsf(x));
                    float vv = lg2f(1.0f + uu);
                    float sp = fmaf(C_LN2, vv, fmaxf(x, 0.0f));
                    P[ii * 2 + jj] *= fmaxf(sp, 2e-23f);
                }
            }
        }

#pragma unroll
        for (int ii = 0; ii < 4; ii++) {
            const int i = i0 + ii;
#pragma unroll
            for (int jj = 0; jj < 2; jj++) {
                const int j = j0 + jj;
                if (j <= i) {
                    float Pv = P[ii * 2 + jj];
                    float cij = Pv * srcp[j];
                    cij = fminf(fmaxf(cij, 1e-6f), 1.0f - 1e-6f);
                    float cji = Pv * srcp[i];
                    cji = fminf(fmaxf(cji, 1e-6f), 1.0f - 1e-6f);
                    sc[i * K_SZ + j] = cij;
                    sc[j * K_SZ + i] = cji;
                }
            }
        }
    }
    __syncthreads();

    // coalesced cond writeout + flat_rel @ Wrel
    float acc = 0.0f;
    float4* condout = (float4*)(out + OUT_COND_OFF + (size_t)b * (K_SZ * K_SZ));
    for (int q = tid; q < (K_SZ * K_SZ) / 4; q += 256) {
        float4 v = *(const float4*)&sc[q * 4];
        float4 w = *(const float4*)&sw[q * 4];
        condout[q] = v;
        acc += v.x * w.x + v.y * w.y + v.z * w.z + v.w * w.w;
    }

#pragma unroll
    for (int off = 16; off > 0; off >>= 1)
        acc += __shfl_down_sync(0xffffffffu, acc, off);
    if ((tid & 31) == 0) rr[tid >> 5] = acc;
    __syncthreads();
    if (tid == 0) {
        float s = 0.0f;
#pragma unroll
        for (int w = 0; w < 8; w++) s += rr[w];
        float logit = sbox[0] + sbox[1] + bbox[0] + s + brel[0];
        out[b] = sigmoid_f(logit);
    }
}

// ---------------------------------------------------------------------------
extern "C" void kernel_launch(void* const* d_in, const int* in_sizes, int n_in,
                              void* d_out, int out_size)
{
    const float* features = (const float*)d_in[0];
    const float* Wp       = (const float*)d_in[1];
    const float* bp       = (const float*)d_in[2];
    const float* Wprob    = (const float*)d_in[3];
    const float* bprob    = (const float*)d_in[4];
    const float* Wbox     = (const float*)d_in[5];
    const float* bbox     = (const float*)d_in[6];
    const float* Wrel     = (const float*)d_in[7];
    const float* brel     = (const float*)d_in[8];
    float* out = (float*)d_out;

    cudaFuncSetAttribute(gemm_bf16, cudaFuncAttributeMaxDynamicSharedMemorySize, SMEM_BYTES);

    convert_A<<<(B_SZ * F_SZ / 4) / 256, 256>>>(features);
    convert_B<<<(F_SZ / 2) * N_SZ / 256, 256>>>(Wp);
    gemm_bf16<<<dim3(8, 32), 256, SMEM_BYTES>>>();
    fused_kernel<<<B_SZ, 256>>>(bp, Wprob, bprob, Wbox, Wrel, bbox, brel, out);
}

// round 11
// speedup vs baseline: 2.1586x; 1.0360x over previous
#include <cuda_runtime.h>
#include <cuda_bf16.h>
#include <math.h>
#include <stdint.h>

// ---------------------------------------------------------------------------
// Problem constants
// ---------------------------------------------------------------------------
#define B_SZ 4096
#define K_SZ 64
#define D_SZ 8
#define F_SZ 2048
#define N_SZ 1024
#define NPAIR (K_SZ * (K_SZ + 1) / 2)
#define NTILE 272                 // 4x2 pair tiles covering lower triangle

#define OUT_CONCEPT_OFF (B_SZ)
#define OUT_COND_OFF (B_SZ + B_SZ * K_SZ)

// GEMM tiling: block 128x128, BK=32 (16 bf16x2 words), 2-stage cp.async pipe
#define GITERS (F_SZ / 32)        // 64
#define ASTRIDE 20
#define BSTRIDE 136
#define A_PLANE_W (128 * ASTRIDE)
#define B_PLANE_W (16 * BSTRIDE)
#define STAGE_W (2 * A_PLANE_W + 2 * B_PLANE_W)
#define SMEM_BYTES (2 * STAGE_W * 4)             // 75776 B -> 2 CTAs/SM

// ---------------------------------------------------------------------------
// Scratch (__device__ globals; no allocation)
// ---------------------------------------------------------------------------
__device__ __align__(256) float g_theta[(size_t)B_SZ * N_SZ];

// pre-split bf16 operands, packed as bf16x2 words
__device__ uint32_t g_AhiW[(size_t)B_SZ * (F_SZ / 2)];
__device__ uint32_t g_AloW[(size_t)B_SZ * (F_SZ / 2)];
__device__ uint32_t g_BhiW[(size_t)(F_SZ / 2) * N_SZ];
__device__ uint32_t g_BloW[(size_t)(F_SZ / 2) * N_SZ];

// ---------------------------------------------------------------------------
// math helpers
// ---------------------------------------------------------------------------
__device__ __forceinline__ float ex2f(float x) {
    float r; asm("ex2.approx.ftz.f32 %0, %1;" : "=f"(r) : "f"(x)); return r;
}
__device__ __forceinline__ float lg2f(float x) {
    float r; asm("lg2.approx.ftz.f32 %0, %1;" : "=f"(r) : "f"(x)); return r;
}
#define C_L2E   1.4426950408889634f
#define C_LN2   0.6931471805599453f

__device__ __forceinline__ float softplus_f(float x) {
    float u = ex2f(-C_L2E * fabsf(x));
    return fmaxf(x, 0.0f) + C_LN2 * lg2f(1.0f + u);
}
__device__ __forceinline__ float sigmoid_f(float x) {
    return 1.0f / (1.0f + ex2f(-C_L2E * x));
}

__device__ __forceinline__ void mma_bf16(float* c, const uint32_t* a, const uint32_t* b) {
    asm volatile(
        "mma.sync.aligned.m16n8k16.row.col.f32.bf16.bf16.f32 "
        "{%0,%1,%2,%3}, {%4,%5,%6,%7}, {%8,%9}, {%0,%1,%2,%3};"
        : "+f"(c[0]), "+f"(c[1]), "+f"(c[2]), "+f"(c[3])
        : "r"(a[0]), "r"(a[1]), "r"(a[2]), "r"(a[3]), "r"(b[0]), "r"(b[1]));
}

// cp.async (portable sm_80+ PTX)
__device__ __forceinline__ void cp16(uint32_t saddr, const void* gptr) {
    asm volatile("cp.async.cg.shared.global [%0], [%1], 16;"
                 :: "r"(saddr), "l"((unsigned long long)__cvta_generic_to_global(gptr))
                 : "memory");
}
__device__ __forceinline__ void cp_commit() {
    asm volatile("cp.async.commit_group;" ::: "memory");
}
template <int N>
__device__ __forceinline__ void cp_wait() {
    asm volatile("cp.async.wait_group %0;" :: "n"(N) : "memory");
}

__device__ __forceinline__ uint32_t pack_hi(float x, float y) {
    __nv_bfloat162 v = __halves2bfloat162(__float2bfloat16(x), __float2bfloat16(y));
    return *(uint32_t*)&v;
}
__device__ __forceinline__ uint32_t pack_lo(float x, float y) {
    __nv_bfloat16 hx = __float2bfloat16(x);
    __nv_bfloat16 hy = __float2bfloat16(y);
    __nv_bfloat162 v = __halves2bfloat162(__float2bfloat16(x - __bfloat162float(hx)),
                                          __float2bfloat16(y - __bfloat162float(hy)));
    return *(uint32_t*)&v;
}

// ---------------------------------------------------------------------------
// Convert A: fp32 [4096,2048] -> packed bf16x2 hi/lo word arrays
// ---------------------------------------------------------------------------
__global__ __launch_bounds__(256)
void convert_A(const float* __restrict__ A)
{
    int gid = blockIdx.x * 256 + threadIdx.x;
    float4 v = *(const float4*)(A + (size_t)gid * 4);
    uint2 hi = make_uint2(pack_hi(v.x, v.y), pack_hi(v.z, v.w));
    uint2 lo = make_uint2(pack_lo(v.x, v.y), pack_lo(v.z, v.w));
    *(uint2*)(g_AhiW + (size_t)gid * 2) = hi;
    *(uint2*)(g_AloW + (size_t)gid * 2) = lo;
}

// ---------------------------------------------------------------------------
// Convert B: Wp[k][f][d] (n = k*16+d) -> word(fw, n) arrays
// ---------------------------------------------------------------------------
__global__ __launch_bounds__(256)
void convert_B(const float* __restrict__ Wp)
{
    int gid = blockIdx.x * 256 + threadIdx.x;
    int fw = gid >> 10;
    int n  = gid & 1023;
    int k = n >> 4, d = n & 15;
    const float* base = Wp + (size_t)k * (F_SZ * 16) + d;
    float x = base[(size_t)(2 * fw) * 16];
    float y = base[(size_t)(2 * fw + 1) * 16];
    g_BhiW[gid] = pack_hi(x, y);
    g_BloW[gid] = pack_lo(x, y);
}

// ---------------------------------------------------------------------------
// bf16 3-pass tensor-core GEMM with cp.async pipeline, 2 CTAs/SM.
// Block 128x128, 8 warps (2m x 4n), warp tile 64x32, BK=32.
// ---------------------------------------------------------------------------
#define AS_IDX(s,p,m,kw) ((s) * STAGE_W + (p) * A_PLANE_W + (m) * ASTRIDE + (kw))
#define BS_IDX(s,p,kw,n) ((s) * STAGE_W + 2 * A_PLANE_W + (p) * B_PLANE_W + (kw) * BSTRIDE + (n))

__global__ __launch_bounds__(256, 2)
void gemm_bf16()
{
    extern __shared__ uint32_t sm[];
    const uint32_t smb = (uint32_t)__cvta_generic_to_shared(sm);

    const int tid  = threadIdx.x;
    const int lane = tid & 31;
    const int warp = tid >> 5;
    const int wm = warp & 1;
    const int wn = warp >> 1;
    const int bx = blockIdx.x;
    const int by = blockIdx.y;

    // global load mapping
    const int am  = tid >> 1;            // 0..127
    const int akw = (tid & 1) * 8;       // 0 or 8
    const uint32_t* ApH = g_AhiW + (size_t)(by * 128 + am) * (F_SZ / 2) + akw;
    const uint32_t* ApL = g_AloW + (size_t)(by * 128 + am) * (F_SZ / 2) + akw;
    const int bfw = tid >> 4;            // 0..15
    const int bnf = (tid & 15) * 8;      // 0..120
    const uint32_t* BpH = g_BhiW + (size_t)bfw * N_SZ + bx * 128 + bnf;
    const uint32_t* BpL = g_BloW + (size_t)bfw * N_SZ + bx * 128 + bnf;

    // this thread's smem store addresses (stage 0; stage 1 = +STAGE_W*4)
    const uint32_t sAh = smb + 4 * AS_IDX(0, 0, am, akw);
    const uint32_t sAl = smb + 4 * AS_IDX(0, 1, am, akw);
    const uint32_t sBh = smb + 4 * BS_IDX(0, 0, bfw, bnf);
    const uint32_t sBl = smb + 4 * BS_IDX(0, 1, bfw, bnf);

    float acc[4][4][4];
#pragma unroll
    for (int i = 0; i < 4; i++)
#pragma unroll
        for (int j = 0; j < 4; j++)
#pragma unroll
            for (int r = 0; r < 4; r++) acc[i][j][r] = 0.0f;

#define ISSUE(it, s) do {                                                     \
        const int kb_ = (it) * 16;                                            \
        const uint32_t so_ = (s) * (STAGE_W * 4);                             \
        cp16(sAh + so_,      ApH + kb_);                                      \
        cp16(sAh + so_ + 16, ApH + kb_ + 4);                                  \
        cp16(sAl + so_,      ApL + kb_);                                      \
        cp16(sAl + so_ + 16, ApL + kb_ + 4);                                  \
        const size_t gb_ = (size_t)kb_ * N_SZ;                                \
        cp16(sBh + so_,      BpH + gb_);                                      \
        cp16(sBh + so_ + 16, BpH + gb_ + 4);                                  \
        cp16(sBl + so_,      BpL + gb_);                                      \
        cp16(sBl + so_ + 16, BpL + gb_ + 4);                                  \
        cp_commit();                                                          \
    } while (0)

    ISSUE(0, 0);
    ISSUE(1, 1);

    const int ar = lane >> 2;
    const int aq = lane & 3;
    const int bq = lane & 3;
    const int bc = lane >> 2;

    for (int it = 0; it < GITERS; ++it) {
        const int s = it & 1;

        if (it < GITERS - 1) cp_wait<1>(); else cp_wait<0>();
        __syncthreads();

#pragma unroll
        for (int ks = 0; ks < 2; ++ks) {
            const int kwb = ks * 8;
            uint32_t bh[4][2], bl[4][2];
#pragma unroll
            for (int nt = 0; nt < 4; ++nt) {
                const int n = wn * 32 + nt * 8 + bc;
                bh[nt][0] = sm[BS_IDX(s, 0, kwb + bq,     n)];
                bh[nt][1] = sm[BS_IDX(s, 0, kwb + bq + 4, n)];
                bl[nt][0] = sm[BS_IDX(s, 1, kwb + bq,     n)];
                bl[nt][1] = sm[BS_IDX(s, 1, kwb + bq + 4, n)];
            }
#pragma unroll
            for (int mt = 0; mt < 4; ++mt) {
                const int row = wm * 64 + mt * 16 + ar;
                uint32_t ah[4], al[4];
                ah[0] = sm[AS_IDX(s, 0, row,     kwb + aq)];
                ah[1] = sm[AS_IDX(s, 0, row + 8, kwb + aq)];
                ah[2] = sm[AS_IDX(s, 0, row,     kwb + aq + 4)];
                ah[3] = sm[AS_IDX(s, 0, row + 8, kwb + aq + 4)];
                al[0] = sm[AS_IDX(s, 1, row,     kwb + aq)];
                al[1] = sm[AS_IDX(s, 1, row + 8, kwb + aq)];
                al[2] = sm[AS_IDX(s, 1, row,     kwb + aq + 4)];
                al[3] = sm[AS_IDX(s, 1, row + 8, kwb + aq + 4)];
#pragma unroll
                for (int nt = 0; nt < 4; ++nt) {
                    mma_bf16(acc[mt][nt], ah, bh[nt]);
                    mma_bf16(acc[mt][nt], ah, bl[nt]);
                    mma_bf16(acc[mt][nt], al, bh[nt]);
                }
            }
        }

        __syncthreads();
        if (it + 2 < GITERS) ISSUE(it + 2, s);
    }
#undef ISSUE

    // epilogue
    const int mbase = by * 128 + wm * 64 + (lane >> 2);
    const int nbase = bx * 128 + wn * 32 + (lane & 3) * 2;
#pragma unroll
    for (int mt = 0; mt < 4; ++mt) {
#pragma unroll
        for (int nt = 0; nt < 4; ++nt) {
            const int m = mbase + mt * 16;
            const int n = nbase + nt * 8;
            float* p = g_theta + (size_t)m * N_SZ + n;
            p[0] = acc[mt][nt][0];
            p[1] = acc[mt][nt][1];
            p[(size_t)8 * N_SZ]     = acc[mt][nt][2];
            p[(size_t)8 * N_SZ + 1] = acc[mt][nt][3];
        }
    }
}

// ---------------------------------------------------------------------------
// Fused box + pair kernel (unchanged from R10 — at MUFU floor)
// ---------------------------------------------------------------------------
__global__ __launch_bounds__(256)
void fused_kernel(const float* __restrict__ bp, const float* __restrict__ Wprob,
                  const float* __restrict__ bprob, const float* __restrict__ Wbox,
                  const float* __restrict__ Wrel, const float* __restrict__ bbox,
                  const float* __restrict__ brel, float* __restrict__ out)
{
    const int b = blockIdx.x;
    const int tid = threadIdx.x;

    __shared__ __align__(16) float szt[D_SZ * K_SZ];   // [d][k]
    __shared__ __align__(16) float sZt[D_SZ * K_SZ];   // [d][k]
    __shared__ __align__(16) float srcp[K_SZ];
    __shared__ __align__(16) float sw[K_SZ * K_SZ];
    __shared__ __align__(16) float sc[K_SZ * K_SZ];
    __shared__ __align__(16) uint16_t stbl[NTILE];
    __shared__ float sbox[2];
    __shared__ float rr[8];

    if (tid >= 64) {
        for (int i = tid - 64; i < K_SZ * K_SZ; i += 192) sw[i] = Wrel[i];
    } else {
        // ---- box phase: one thread per k ----
        const int k = tid;
        const int lane = tid & 31;
        const float4* th4 = (const float4*)(g_theta + (size_t)b * N_SZ + k * 16);
        const float4* bp4 = (const float4*)(bp + k * 16);
        float4 t0 = th4[0], t1 = th4[1], t2 = th4[2], t3 = th4[3];
        float4 b0 = bp4[0], b1 = bp4[1], b2 = bp4[2], b3 = bp4[3];

        float z[8], Zb[8];
        float tz[8] = { t0.x + b0.x, t0.y + b0.y, t0.z + b0.z, t0.w + b0.w,
                        t1.x + b1.x, t1.y + b1.y, t1.z + b1.z, t1.w + b1.w };
        float tu[8] = { t2.x + b2.x, t2.y + b2.y, t2.z + b2.z, t2.w + b2.w,
                        t3.x + b3.x, t3.y + b3.y, t3.z + b3.z, t3.w + b3.w };
#pragma unroll
        for (int d = 0; d < 8; d++) {
            z[d]  = tz[d];
            Zb[d] = tz[d] + softplus_f(tu[d]);
        }

        // concept prob
        const float4* wp4 = (const float4*)(Wprob + k * 16);
        float4 w0 = wp4[0], w1 = wp4[1], w2 = wp4[2], w3 = wp4[3];
        const float wz[8] = { w0.x, w0.y, w0.z, w0.w, w1.x, w1.y, w1.z, w1.w };
        const float wZ[8] = { w2.x, w2.y, w2.z, w2.w, w3.x, w3.y, w3.z, w3.w };
        float logit = bprob[k];
#pragma unroll
        for (int d = 0; d < 8; d++)
            logit += z[d] * wz[d] + Zb[d] * wZ[d];
        float p = sigmoid_f(logit);
        out[OUT_CONCEPT_OFF + b * K_SZ + k] = p;

        // box volume, unscaled sides
        float P = 1.0f;
#pragma unroll
        for (int d = 0; d < 8; d++) {
            float x = 2.0f * (Zb[d] - z[d]);
            float u = ex2f(-C_L2E * x);
            float sp = x + C_LN2 * lg2f(1.0f + u);
            P *= fmaxf(sp, 2e-23f);
        }
        srcp[k] = 1.0f / P;

        // transposed stash
#pragma unroll
        for (int d = 0; d < 8; d++) { szt[d * K_SZ + k] = z[d]; sZt[d * K_SZ + k] = Zb[d]; }

        // box part of final logit
        const float4* wb4 = (const float4*)(Wbox + k * 16);
        float4 v0 = wb4[0], v1 = wb4[1], v2 = wb4[2], v3 = wb4[3];
        const float wbz[8] = { v0.x, v0.y, v0.z, v0.w, v1.x, v1.y, v1.z, v1.w };
        const float wbZ[8] = { v2.x, v2.y, v2.z, v2.w, v3.x, v3.y, v3.z, v3.w };
        float c = 0.0f;
#pragma unroll
        for (int d = 0; d < 8; d++)
            c += z[d] * wbz[d] + Zb[d] * wbZ[d];
        c *= p;
#pragma unroll
        for (int off = 16; off > 0; off >>= 1)
            c += __shfl_down_sync(0xffffffffu, c, off);
        if (lane == 0) sbox[tid >> 5] = c;

        // tile table
        if (k < 16) {
            const int ti = k;
            const int base = ti * ti + ti;
            for (int tj = 0; tj <= 2 * ti + 1; tj++)
                stbl[base + tj] = (uint16_t)((ti << 6) | tj);
        }
    }
    __syncthreads();

    // ---- pair phase: one 4x2 tile (8 pairs) per unit ----
    for (int u = tid; u < NTILE; u += 256) {
        const int v = stbl[u];
        const int i0 = (v >> 6) * 4;
        const int j0 = (v & 63) * 2;

        float P[8];
#pragma unroll
        for (int q = 0; q < 8; q++) P[q] = 1.0f;

#pragma unroll 1
        for (int d = 0; d < 8; d++) {
            const float* zr = szt + d * K_SZ;
            const float* Zr = sZt + d * K_SZ;
            float zi[4], Zi[4], zj[2], Zj[2];
#pragma unroll
            for (int ii = 0; ii < 4; ii++) { zi[ii] = zr[i0 + ii]; Zi[ii] = Zr[i0 + ii]; }
#pragma unroll
            for (int jj = 0; jj < 2; jj++) { zj[jj] = zr[j0 + jj]; Zj[jj] = Zr[j0 + jj]; }

#pragma unroll
            for (int ii = 0; ii < 4; ii++) {
#pragma unroll
                for (int jj = 0; jj < 2; jj++) {
                    float d1 = zi[ii] - zj[jj];
                    float d2 = Zi[ii] - Zj[jj];
                    float e1 = ex2f(-10.0f * C_L2E * fabsf(d1));
                    float e2 = ex2f(-10.0f * C_L2E * fabsf(d2));
                    float s  = fmaf(e1, e2, e1) + e2;
                    float t2 = lg2f(1.0f + s);
                    float gap = fminf(Zi[ii], Zj[jj]) - fmaxf(zi[ii], zj[jj]);
                    float x  = fmaf(-0.2f * C_LN2, t2, gap + gap);
                    float uu = ex2f(-C_L2E * fabsf(x));
                    float vv = lg2f(1.0f + uu);
                    float sp = fmaf(C_LN2, vv, fmaxf(x, 0.0f));
                    P[ii * 2 + jj] *= fmaxf(sp, 2e-23f);
                }
            }
        }

#pragma unroll
        for (int ii = 0; ii < 4; ii++) {
            const int i = i0 + ii;
#pragma unroll
            for (int jj = 0; jj < 2; jj++) {
                const int j = j0 + jj;
                if (j <= i) {
                    float Pv = P[ii * 2 + jj];
                    float cij = Pv * srcp[j];
                    cij = fminf(fmaxf(cij, 1e-6f), 1.0f - 1e-6f);
                    float cji = Pv * srcp[i];
                    cji = fminf(fmaxf(cji, 1e-6f), 1.0f - 1e-6f);
                    sc[i * K_SZ + j] = cij;
                    sc[j * K_SZ + i] = cji;
                }
            }
        }
    }
    __syncthreads();

    // coalesced cond writeout + flat_rel @ Wrel
    float acc = 0.0f;
    float4* condout = (float4*)(out + OUT_COND_OFF + (size_t)b * (K_SZ * K_SZ));
    for (int q = tid; q < (K_SZ * K_SZ) / 4; q += 256) {
        float4 v = *(const float4*)&sc[q * 4];
        float4 w = *(const float4*)&sw[q * 4];
        condout[q] = v;
        acc += v.x * w.x + v.y * w.y + v.z * w.z + v.w * w.w;
    }

#pragma unroll
    for (int off = 16; off > 0; off >>= 1)
        acc += __shfl_down_sync(0xffffffffu, acc, off);
    if ((tid & 31) == 0) rr[tid >> 5] = acc;
    __syncthreads();
    if (tid == 0) {
        float s = 0.0f;
#pragma unroll
        for (int w = 0; w < 8; w++) s += rr[w];
        float logit = sbox[0] + sbox[1] + bbox[0] + s + brel[0];
        out[b] = sigmoid_f(logit);
    }
}

// ---------------------------------------------------------------------------
extern "C" void kernel_launch(void* const* d_in, const int* in_sizes, int n_in,
                              void* d_out, int out_size)
{
    const float* features = (const float*)d_in[0];
    const float* Wp       = (const float*)d_in[1];
    const float* bp       = (const float*)d_in[2];
    const float* Wprob    = (const float*)d_in[3];
    const float* bprob    = (const float*)d_in[4];
    const float* Wbox     = (const float*)d_in[5];
    const float* bbox     = (const float*)d_in[6];
    const float* Wrel     = (const float*)d_in[7];
    const float* brel     = (const float*)d_in[8];
    float* out = (float*)d_out;

    cudaFuncSetAttribute(gemm_bf16, cudaFuncAttributeMaxDynamicSharedMemorySize, SMEM_BYTES);

    convert_A<<<(B_SZ * F_SZ / 4) / 256, 256>>>(features);
    convert_B<<<(F_SZ / 2) * N_SZ / 256, 256>>>(Wp);
    gemm_bf16<<<dim3(8, 32), 256, SMEM_BYTES>>>();
    fused_kernel<<<B_SZ, 256>>>(bp, Wprob, bprob, Wbox, Wrel, bbox, brel, out);
}